// round 8
// baseline (speedup 1.0000x reference)
#include <cuda_runtime.h>
#include <cuda_bf16.h>
#include <math.h>
#include <stdint.h>

// Problem constants
#define Bx  2
#define Lx  2048
#define Dx  1024
#define Hx  16
#define DKx 64
#define BHx (Bx*Hx)

// ---------------- device scratch (no allocations allowed) ----------------
__device__ float g_Q[(size_t)BHx*Lx*DKx];      // [B,H,L,DK]
__device__ float g_K[(size_t)BHx*Lx*DKx];
__device__ float g_V[(size_t)BHx*Lx*DKx];
__device__ float g_attn[(size_t)Bx*Lx*Dx];     // [B,L,H*DK]
__device__ float g_bias[(size_t)Bx*Lx*Lx];     // -|lam|*log1p(|ti-tj|/denom)
__device__ float g_scal[2];                    // [0]=1/denom, [1]=-|lam|
// packed bf16 hi/lo operands (u32 = bf16x2 pair along k)
__device__ uint32_t g_xh[(size_t)4096*512], g_xl[(size_t)4096*512];   // x, later attn-out
__device__ uint32_t g_wh[(size_t)4*1024*512], g_wl[(size_t)4*1024*512];

// ---------------- helpers ----------------
__device__ __forceinline__ uint32_t to_tf32(float x) {
    uint32_t r;
    asm("cvt.rna.tf32.f32 %0, %1;" : "=r"(r) : "f"(x));
    return r;
}
__device__ __forceinline__ float tf32f(float x) { return __uint_as_float(to_tf32(x)); }

// split two floats into packed bf16x2 hi and lo
__device__ __forceinline__ void split2(float2 v, uint32_t& hi, uint32_t& lo) {
    __nv_bfloat162 h = __floats2bfloat162_rn(v.x, v.y);
    float hx = __bfloat162float(h.x);
    float hy = __bfloat162float(h.y);
    __nv_bfloat162 l = __floats2bfloat162_rn(v.x - hx, v.y - hy);
    hi = *(uint32_t*)&h;
    lo = *(uint32_t*)&l;
}

__device__ __forceinline__ void mma16n8k8(float* c, const uint32_t* a, const uint32_t* b) {
    asm volatile(
        "mma.sync.aligned.m16n8k8.row.col.f32.tf32.tf32.f32 "
        "{%0,%1,%2,%3}, {%4,%5,%6,%7}, {%8,%9}, {%0,%1,%2,%3};"
        : "+f"(c[0]), "+f"(c[1]), "+f"(c[2]), "+f"(c[3])
        : "r"(a[0]), "r"(a[1]), "r"(a[2]), "r"(a[3]), "r"(b[0]), "r"(b[1]));
}
__device__ __forceinline__ void mma_bf16(float* c, const uint32_t* a, uint32_t b0, uint32_t b1) {
    asm volatile(
        "mma.sync.aligned.m16n8k16.row.col.f32.bf16.bf16.f32 "
        "{%0,%1,%2,%3}, {%4,%5,%6,%7}, {%8,%9}, {%0,%1,%2,%3};"
        : "+f"(c[0]), "+f"(c[1]), "+f"(c[2]), "+f"(c[3])
        : "r"(a[0]), "r"(a[1]), "r"(a[2]), "r"(a[3]), "r"(b0), "r"(b1));
}
__device__ __forceinline__ void ldm_x4(uint32_t& r0, uint32_t& r1, uint32_t& r2, uint32_t& r3,
                                       uint32_t addr) {
    asm volatile("ldmatrix.sync.aligned.m8n8.x4.shared.b16 {%0,%1,%2,%3}, [%4];"
                 : "=r"(r0), "=r"(r1), "=r"(r2), "=r"(r3) : "r"(addr));
}

__device__ __forceinline__ void cpasync16(uint32_t s, const void* g) {
    asm volatile("cp.async.cg.shared.global [%0], [%1], 16;" :: "r"(s), "l"(g));
}
__device__ __forceinline__ uint32_t smem_u32p(const void* p) {
    uint32_t a;
    asm("{ .reg .u64 t; cvta.to.shared.u64 t, %1; cvt.u32.u64 %0, t; }" : "=r"(a) : "l"(p));
    return a;
}

// Fast exp on the FMA pipe
__device__ __forceinline__ float fexp(float x) {
    x = fmaxf(x, -80.0f);
    float z = fmaf(x, 1.4426950408889634f, 12582912.0f);
    int   ni = __float_as_int(z) - 0x4B400000;
    float fn = z - 12582912.0f;
    float f  = fmaf(x, 1.4426950408889634f, -fn);
    float p = 0.0013333558f;
    p = fmaf(p, f, 0.0096181291f);
    p = fmaf(p, f, 0.0555041087f);
    p = fmaf(p, f, 0.2402265069f);
    p = fmaf(p, f, 0.6931471806f);
    p = fmaf(p, f, 1.0f);
    return __int_as_float(__float_as_int(p) + (ni << 23));
}

// ---------------- denom + lam scalars ----------------
__global__ void k_denom(const float* __restrict__ ts, const float* __restrict__ lam)
{
    float m = 1.0f;
    for (int b = 0; b < Bx; b++) {
        float d = ts[b*Lx + (Lx-1)] - ts[b*Lx + 0];
        m = fmaxf(m, d);
    }
    g_scal[0] = 1.0f / m;
    g_scal[1] = -fabsf(lam[0]);
}

// ---------------- temporal bias precompute ----------------
__global__ __launch_bounds__(256) void k_bias(const float* __restrict__ ts)
{
    long idx = (long)blockIdx.x * 256 + threadIdx.x;
    int  j = (int)(idx & (Lx-1));
    long t = idx >> 11;
    int  i = (int)(t & (Lx-1));
    int  b = (int)(t >> 11);
    float d = fabsf(ts[b*Lx + i] - ts[b*Lx + j]);
    g_bias[idx] = g_scal[1] * log1pf(d * g_scal[0]);
}

// ---------------- pack fp32 -> bf16 hi/lo pairs ----------------
__global__ __launch_bounds__(256) void k_pack(const float* __restrict__ s,
                                              uint32_t* __restrict__ h,
                                              uint32_t* __restrict__ l)
{
    int i = blockIdx.x * 256 + threadIdx.x;
    float2 v = *(const float2*)(s + 2 * (size_t)i);
    split2(v, h[i], l[i]);
}
__global__ __launch_bounds__(256) void k_packw(const float* __restrict__ w0,
                                               const float* __restrict__ w1,
                                               const float* __restrict__ w2,
                                               const float* __restrict__ w3)
{
    const float* s = (blockIdx.z == 0) ? w0 : (blockIdx.z == 1) ? w1 :
                     (blockIdx.z == 2) ? w2 : w3;
    size_t off = (size_t)blockIdx.z * 1024 * 512;
    int i = blockIdx.x * 256 + threadIdx.x;
    float2 v = *(const float2*)(s + 2 * (size_t)i);
    split2(v, g_wh[off + i], g_wl[off + i]);
}

// ---------------- bf16 hi/lo 3-term GEMM, cp.async + ldmatrix ----------------
// out[m,n] = sum_k A[m,k]*W[n,k] + bias[n];  A,W pre-packed bf16 hi/lo pairs.
// BM=BN=128, BK=32 (16 u32 pairs). 256 threads = 8 warps (2m x 4n), warp tile 64x32.
#define GLD 20                         // padded row stride in u32 (16 data + 4 pad)
#define GST (128 * GLD)                // u32 per matrix tile per stage
#define GSTAGE (4 * GST)               // Ah|Al|Bh|Bl
#define GEMM2_SMEM (2 * GSTAGE * 4)    // 81920 B

template<bool SCATTER>
__global__ __launch_bounds__(256, 2) void k_gemm_bf16(
    const float* __restrict__ b0, const float* __restrict__ b1,
    const float* __restrict__ b2, float* __restrict__ outp)
{
    extern __shared__ uint32_t smu[];
    const uint32_t sb = smem_u32p(smu);

    const float* bias;
    float* out;
    int widx;
    if (SCATTER) {
        widx = blockIdx.z;
        if (widx == 0)      { bias = b0; out = g_Q; }
        else if (widx == 1) { bias = b1; out = g_K; }
        else                { bias = b2; out = g_V; }
    } else {
        widx = 3; bias = b0; out = outp;
    }
    const uint32_t* Ah = g_xh;
    const uint32_t* Al = g_xl;
    const uint32_t* Bh = g_wh + (size_t)widx * 1024 * 512;
    const uint32_t* Bl = g_wl + (size_t)widx * 1024 * 512;

    const int tid = threadIdx.x;
    const int wid = tid >> 5, lane = tid & 31;
    const int wm = wid >> 2, wn = wid & 3;
    const int lr = lane >> 2, lc = lane & 3;
    const int m0 = blockIdx.y * 128;
    const int n0 = blockIdx.x * 128;

    // ldmatrix per-lane addressing: group g = lane>>3
    //  g0: rows +0..7  k-lo | g1: rows +8..15 k-lo | g2: rows +0..7 k-hi | g3: rows +8..15 k-hi
    const int grp  = lane >> 3;
    const int rofs = (lane & 7) + (grp & 1) * 8;
    const int cofs = (grp >> 1) * 4;               // u32 offset (8 bf16)

    float c[4][4][4];
#pragma unroll
    for (int i = 0; i < 4; i++)
#pragma unroll
        for (int j = 0; j < 4; j++)
#pragma unroll
            for (int q = 0; q < 4; q++) c[i][j][q] = 0.f;

    auto load_stage = [&](int st, int kp0) {
        const uint32_t base = sb + st * GSTAGE * 4;
#pragma unroll
        for (int t = 0; t < 2; t++) {
            int i = tid + t * 256;
            int r = i >> 2, cc = i & 3;
            size_t ga = (size_t)(m0 + r) * 512 + kp0 + cc * 4;
            uint32_t ds = (r * GLD + cc * 4) * 4;
            cpasync16(base + ds,               Ah + ga);
            cpasync16(base + GST * 4 + ds,     Al + ga);
            size_t gb = (size_t)(n0 + r) * 512 + kp0 + cc * 4;
            cpasync16(base + 2 * GST * 4 + ds, Bh + gb);
            cpasync16(base + 3 * GST * 4 + ds, Bl + gb);
        }
        asm volatile("cp.async.commit_group;");
    };

    load_stage(0, 0);

    const int NITER = 32;                 // 1024 / 32
    for (int it = 0; it < NITER; ++it) {
        const int buf = it & 1;
        if (it + 1 < NITER) {
            load_stage(1 - buf, (it + 1) * 16);
            asm volatile("cp.async.wait_group 1;");
        } else {
            asm volatile("cp.async.wait_group 0;");
        }
        __syncthreads();

        const uint32_t base = sb + buf * GSTAGE * 4;
        const uint32_t aHb = base + ((wm * 64 + rofs) * GLD + cofs) * 4;
        const uint32_t aLb = aHb + GST * 4;
        const uint32_t bHb = base + 2 * GST * 4 + ((wn * 32 + rofs) * GLD + cofs) * 4;
        const uint32_t bLb = bHb + GST * 4;

#pragma unroll
        for (int ks = 0; ks < 2; ks++) {
            const uint32_t ko = ks * 8 * 4;
            uint32_t bH[4][2], bL[4][2];
#pragma unroll
            for (int p = 0; p < 2; p++) {
                uint32_t r0, r1, r2, r3;
                ldm_x4(r0, r1, r2, r3, bHb + p * 16 * GLD * 4 + ko);
                bH[2*p][0] = r0; bH[2*p+1][0] = r1; bH[2*p][1] = r2; bH[2*p+1][1] = r3;
                ldm_x4(r0, r1, r2, r3, bLb + p * 16 * GLD * 4 + ko);
                bL[2*p][0] = r0; bL[2*p+1][0] = r1; bL[2*p][1] = r2; bL[2*p+1][1] = r3;
            }
#pragma unroll
            for (int mt = 0; mt < 4; mt++) {
                uint32_t aH[4], aL[4];
                ldm_x4(aH[0], aH[1], aH[2], aH[3], aHb + mt * 16 * GLD * 4 + ko);
                ldm_x4(aL[0], aL[1], aL[2], aL[3], aLb + mt * 16 * GLD * 4 + ko);
#pragma unroll
                for (int nt = 0; nt < 4; nt++) {
                    mma_bf16(c[mt][nt], aH, bH[nt][0], bH[nt][1]);
                    mma_bf16(c[mt][nt], aH, bL[nt][0], bL[nt][1]);
                    mma_bf16(c[mt][nt], aL, bH[nt][0], bH[nt][1]);
                }
            }
        }
        __syncthreads();
    }

    // epilogue: add bias, store
#pragma unroll
    for (int mt = 0; mt < 4; mt++) {
        const int mA = m0 + wm * 64 + mt * 16 + lr;
        const int mB = mA + 8;
#pragma unroll
        for (int nt = 0; nt < 4; nt++) {
            const int n = n0 + wn * 32 + nt * 8 + 2 * lc;
            const float bn0 = bias[n], bn1 = bias[n + 1];
            float2 v0 = make_float2(c[mt][nt][0] + bn0, c[mt][nt][1] + bn1);
            float2 v1 = make_float2(c[mt][nt][2] + bn0, c[mt][nt][3] + bn1);
            if (SCATTER) {
                const int h = n >> 6, dk = n & 63;
                const int bA = mA >> 11, lA = mA & (Lx - 1);
                const int bB = mB >> 11, lB = mB & (Lx - 1);
                *(float2*)(out + (((size_t)bA*Hx + h)*Lx + lA)*DKx + dk) = v0;
                *(float2*)(out + (((size_t)bB*Hx + h)*Lx + lB)*DKx + dk) = v1;
            } else {
                *(float2*)(out + (size_t)mA * Dx + n) = v0;
                *(float2*)(out + (size_t)mB * Dx + n) = v1;
            }
        }
    }
}

// ---------------- mma.sync flash attention (unchanged) ----------------
#define AO_KH 0
#define AO_KL 2304
#define AO_V  4608
#define AO_P  9216
#define ATTN_SMEM ((9216 + 4352) * 4)

__global__ __launch_bounds__(128, 3) void k_attn_mma()
{
    extern __shared__ uint32_t smu[];
    uint32_t* KhU = smu + AO_KH;
    uint32_t* KlU = smu + AO_KL;
    float*    Vs  = (float*)(smu + AO_V);
    float*    Ps  = (float*)(smu + AO_P);
    const uint32_t* VsU = (const uint32_t*)Vs;
    const uint32_t* PsU = (const uint32_t*)Ps;

    const int tid = threadIdx.x;
    const int wid = tid >> 5, lane = tid & 31;
    const int lr = lane >> 2, lc = lane & 3;
    const int qt = gridDim.x - 1 - blockIdx.x;
    const int bh = blockIdx.y;
    const int b = bh >> 4, h = bh & 15;
    const int qi0 = qt * 64;
    const int r0 = wid * 16;
    const int qrA = qi0 + r0 + lr;
    const int qrB = qrA + 8;

    const float* Qg = g_Q + (size_t)bh*Lx*DKx;
    const float* Kg = g_K + (size_t)bh*Lx*DKx;
    const float* Vg = g_V + (size_t)bh*Lx*DKx;
    const float* biasB = g_bias + (size_t)b*Lx*Lx;

    uint32_t qH[4][4], qL[4][4];
#pragma unroll
    for (int ks = 0; ks < 4; ks++) {
        const int kb = 16 * ks + 2 * lc;
        float2 v;
        v = *(const float2*)(Qg + (size_t)qrA * DKx + kb);
        split2(v, qH[ks][0], qL[ks][0]);
        v = *(const float2*)(Qg + (size_t)qrB * DKx + kb);
        split2(v, qH[ks][1], qL[ks][1]);
        v = *(const float2*)(Qg + (size_t)qrA * DKx + kb + 8);
        split2(v, qH[ks][2], qL[ks][2]);
        v = *(const float2*)(Qg + (size_t)qrB * DKx + kb + 8);
        split2(v, qH[ks][3], qL[ks][3]);
    }

    float cO[8][4];
#pragma unroll
    for (int nt = 0; nt < 8; nt++)
#pragma unroll
        for (int q = 0; q < 4; q++) cO[nt][q] = 0.f;
    float mA = -1e30f, mB = -1e30f, lA = 0.f, lB = 0.f;

    const int nkt = qt + 1;

    for (int kt = 0; kt < nkt; kt++) {
        const int kj0 = kt * 64;
        __syncthreads();
#pragma unroll
        for (int t = 0; t < 8; t++) {
            int i = tid + t * 128;
            int row = i >> 4, c4 = i & 15;
            float4 kv = *(const float4*)(Kg + (size_t)(kj0 + row) * DKx + c4 * 4);
            uint32_t h0, l0, h1, l1;
            split2(make_float2(kv.x, kv.y), h0, l0);
            split2(make_float2(kv.z, kv.w), h1, l1);
            KhU[row * 36 + c4 * 2]     = h0;
            KhU[row * 36 + c4 * 2 + 1] = h1;
            KlU[row * 36 + c4 * 2]     = l0;
            KlU[row * 36 + c4 * 2 + 1] = l1;
            float4 vv = *(const float4*)(Vg + (size_t)(kj0 + row) * DKx + c4 * 4);
            float* pv = Vs + row * 72 + c4 * 4;
            pv[0] = tf32f(vv.x); pv[1] = tf32f(vv.y);
            pv[2] = tf32f(vv.z); pv[3] = tf32f(vv.w);
        }
        __syncthreads();

        float cS[8][4];
#pragma unroll
        for (int nt = 0; nt < 8; nt++)
#pragma unroll
            for (int q = 0; q < 4; q++) cS[nt][q] = 0.f;

#pragma unroll
        for (int ks = 0; ks < 4; ks++) {
#pragma unroll
            for (int nt = 0; nt < 8; nt++) {
                const uint32_t* ph = KhU + (nt * 8 + lr) * 36 + ks * 8 + lc;
                const uint32_t* pl = KlU + (nt * 8 + lr) * 36 + ks * 8 + lc;
                uint32_t bH0 = ph[0], bH1 = ph[4];
                uint32_t bL0 = pl[0], bL1 = pl[4];
                mma_bf16(cS[nt], qH[ks], bH0, bH1);
                mma_bf16(cS[nt], qH[ks], bL0, bL1);
                mma_bf16(cS[nt], qL[ks], bH0, bH1);
            }
        }

        const bool domask = (kt == qt);
        float rmA = -1e30f, rmB = -1e30f;
#pragma unroll
        for (int nt = 0; nt < 8; nt++) {
            const int kc = kj0 + nt * 8 + 2 * lc;
            float2 biA = *(const float2*)(biasB + (size_t)qrA * Lx + kc);
            float2 biB = *(const float2*)(biasB + (size_t)qrB * Lx + kc);
            float v0 = fmaf(cS[nt][0], 0.125f, biA.x);
            float v1 = fmaf(cS[nt][1], 0.125f, biA.y);
            float v2 = fmaf(cS[nt][2], 0.125f, biB.x);
            float v3 = fmaf(cS[nt][3], 0.125f, biB.y);
            if (domask) {
                if (kc     > qrA) v0 = -1e30f;
                if (kc + 1 > qrA) v1 = -1e30f;
                if (kc     > qrB) v2 = -1e30f;
                if (kc + 1 > qrB) v3 = -1e30f;
            }
            cS[nt][0] = v0; cS[nt][1] = v1; cS[nt][2] = v2; cS[nt][3] = v3;
            rmA = fmaxf(rmA, fmaxf(v0, v1));
            rmB = fmaxf(rmB, fmaxf(v2, v3));
        }
        rmA = fmaxf(rmA, __shfl_xor_sync(0xffffffffu, rmA, 1));
        rmA = fmaxf(rmA, __shfl_xor_sync(0xffffffffu, rmA, 2));
        rmB = fmaxf(rmB, __shfl_xor_sync(0xffffffffu, rmB, 1));
        rmB = fmaxf(rmB, __shfl_xor_sync(0xffffffffu, rmB, 2));

        const float mnA = fmaxf(mA, rmA);
        const float mnB = fmaxf(mB, rmB);
        const float scA = fexp(mA - mnA);
        const float scB = fexp(mB - mnB);
        mA = mnA; mB = mnB;

        float rsA = 0.f, rsB = 0.f;
#pragma unroll
        for (int nt = 0; nt < 8; nt++) {
            float p0 = fexp(cS[nt][0] - mnA);
            float p1 = fexp(cS[nt][1] - mnA);
            float p2 = fexp(cS[nt][2] - mnB);
            float p3 = fexp(cS[nt][3] - mnB);
            rsA += p0 + p1;
            rsB += p2 + p3;
            cS[nt][0] = p0; cS[nt][1] = p1; cS[nt][2] = p2; cS[nt][3] = p3;
        }
        rsA += __shfl_xor_sync(0xffffffffu, rsA, 1);
        rsA += __shfl_xor_sync(0xffffffffu, rsA, 2);
        rsB += __shfl_xor_sync(0xffffffffu, rsB, 1);
        rsB += __shfl_xor_sync(0xffffffffu, rsB, 2);
        lA = lA * scA + rsA;
        lB = lB * scB + rsB;
#pragma unroll
        for (int nt = 0; nt < 8; nt++) {
            cO[nt][0] *= scA; cO[nt][1] *= scA;
            cO[nt][2] *= scB; cO[nt][3] *= scB;
        }

#pragma unroll
        for (int nt = 0; nt < 8; nt++) {
            float* pA = Ps + (r0 + lr) * 68 + nt * 8 + 2 * lc;
            float* pB = Ps + (r0 + lr + 8) * 68 + nt * 8 + 2 * lc;
            pA[0] = tf32f(cS[nt][0]);
            pA[1] = tf32f(cS[nt][1]);
            pB[0] = tf32f(cS[nt][2]);
            pB[1] = tf32f(cS[nt][3]);
        }
        __syncthreads();

#pragma unroll
        for (int ks = 0; ks < 8; ks++) {
            const int k = ks * 8;
            uint32_t aP[4];
            const uint32_t* p = PsU + (r0 + lr) * 68 + k + lc;
            aP[0] = p[0]; aP[2] = p[4]; aP[1] = p[8 * 68]; aP[3] = p[8 * 68 + 4];
#pragma unroll
            for (int nt = 0; nt < 8; nt++) {
                uint32_t bV[2];
                bV[0] = VsU[(k + lc) * 72 + nt * 8 + lr];
                bV[1] = VsU[(k + lc + 4) * 72 + nt * 8 + lr];
                mma16n8k8(cO[nt], aP, bV);
            }
        }
    }

    const float invA = 1.0f / lA;
    const float invB = 1.0f / lB;
    float* oA = g_attn + ((size_t)b * Lx + qrA) * Dx + h * DKx;
    float* oB = g_attn + ((size_t)b * Lx + qrB) * Dx + h * DKx;
#pragma unroll
    for (int nt = 0; nt < 8; nt++) {
        const int n = nt * 8 + 2 * lc;
        *(float2*)(oA + n) = make_float2(cO[nt][0] * invA, cO[nt][1] * invA);
        *(float2*)(oB + n) = make_float2(cO[nt][2] * invB, cO[nt][3] * invB);
    }
}

// ---------------- launch ----------------
extern "C" void kernel_launch(void* const* d_in, const int* in_sizes, int n_in,
                              void* d_out, int out_size)
{
    const float* x   = (const float*)d_in[0];
    const float* ts  = (const float*)d_in[1];
    const float* Wq  = (const float*)d_in[4];
    const float* bq  = (const float*)d_in[5];
    const float* Wk  = (const float*)d_in[6];
    const float* bk  = (const float*)d_in[7];
    const float* Wv  = (const float*)d_in[8];
    const float* bv  = (const float*)d_in[9];
    const float* Wo  = (const float*)d_in[10];
    const float* bo  = (const float*)d_in[11];
    const float* lam = (const float*)d_in[12];
    float* out = (float*)d_out;

    float* xh_f; float* xl_f;
    cudaGetSymbolAddress((void**)&xh_f, g_xh);
    cudaGetSymbolAddress((void**)&xl_f, g_xl);

    k_denom<<<1, 1>>>(ts, lam);
    k_bias<<<(Bx*Lx*Lx)/256, 256>>>(ts);

    // pack x and all 4 weight matrices to bf16 hi/lo
    k_pack<<<(4096*512)/256, 256>>>(x, (uint32_t*)xh_f, (uint32_t*)xl_f);
    k_packw<<<dim3((1024*512)/256, 1, 4), 256>>>(Wq, Wk, Wv, Wo);

    cudaFuncSetAttribute(k_gemm_bf16<true>,  cudaFuncAttributeMaxDynamicSharedMemorySize, GEMM2_SMEM);
    cudaFuncSetAttribute(k_gemm_bf16<false>, cudaFuncAttributeMaxDynamicSharedMemorySize, GEMM2_SMEM);
    cudaFuncSetAttribute(k_attn_mma, cudaFuncAttributeMaxDynamicSharedMemorySize, ATTN_SMEM);

    // Q/K/V projections
    k_gemm_bf16<true><<<dim3(Dx/128, (Bx*Lx)/128, 3), 256, GEMM2_SMEM>>>(
        bq, bk, bv, nullptr);

    // flash attention
    k_attn_mma<<<dim3(Lx/64, BHx), 128, ATTN_SMEM>>>();

    // pack attention output, then output projection
    {
        float* gattn_p;
        cudaGetSymbolAddress((void**)&gattn_p, g_attn);
        k_pack<<<(4096*512)/256, 256>>>(gattn_p, (uint32_t*)xh_f, (uint32_t*)xl_f);
    }
    k_gemm_bf16<false><<<dim3(Dx/128, (Bx*Lx)/128, 1), 256, GEMM2_SMEM>>>(
        bo, nullptr, nullptr, out);
}

// round 9
// speedup vs baseline: 1.1788x; 1.1788x over previous
#include <cuda_runtime.h>
#include <cuda_bf16.h>
#include <math.h>
#include <stdint.h>

// Problem constants
#define Bx  2
#define Lx  2048
#define Dx  1024
#define Hx  16
#define DKx 64
#define BHx (Bx*Hx)

// ---------------- device scratch (no allocations allowed) ----------------
__device__ float g_Q[(size_t)BHx*Lx*DKx];      // [B,H,L,DK]
__device__ float g_K[(size_t)BHx*Lx*DKx];
__device__ float g_V[(size_t)BHx*Lx*DKx];
__device__ float g_attn[(size_t)Bx*Lx*Dx];     // [B,L,H*DK]
__device__ float g_bias[(size_t)Bx*Lx*Lx];     // -|lam|*log1p(|ti-tj|/denom)
__device__ float g_scal[2];                    // [0]=1/denom, [1]=-|lam|

// ---------------- helpers ----------------
__device__ __forceinline__ uint32_t to_tf32(float x) {
    uint32_t r;
    asm("cvt.rna.tf32.f32 %0, %1;" : "=r"(r) : "f"(x));
    return r;
}

// split two floats into packed bf16x2 hi and lo
__device__ __forceinline__ void split2(float2 v, uint32_t& hi, uint32_t& lo) {
    __nv_bfloat162 h = __floats2bfloat162_rn(v.x, v.y);
    float hx = __bfloat162float(h.x);
    float hy = __bfloat162float(h.y);
    __nv_bfloat162 l = __floats2bfloat162_rn(v.x - hx, v.y - hy);
    hi = *(uint32_t*)&h;
    lo = *(uint32_t*)&l;
}

__device__ __forceinline__ void mma16n8k8(float* c, const uint32_t* a, const uint32_t* b) {
    asm volatile(
        "mma.sync.aligned.m16n8k8.row.col.f32.tf32.tf32.f32 "
        "{%0,%1,%2,%3}, {%4,%5,%6,%7}, {%8,%9}, {%0,%1,%2,%3};"
        : "+f"(c[0]), "+f"(c[1]), "+f"(c[2]), "+f"(c[3])
        : "r"(a[0]), "r"(a[1]), "r"(a[2]), "r"(a[3]), "r"(b[0]), "r"(b[1]));
}
__device__ __forceinline__ void mma_bf16(float* c, const uint32_t* a, uint32_t b0, uint32_t b1) {
    asm volatile(
        "mma.sync.aligned.m16n8k16.row.col.f32.bf16.bf16.f32 "
        "{%0,%1,%2,%3}, {%4,%5,%6,%7}, {%8,%9}, {%0,%1,%2,%3};"
        : "+f"(c[0]), "+f"(c[1]), "+f"(c[2]), "+f"(c[3])
        : "r"(a[0]), "r"(a[1]), "r"(a[2]), "r"(a[3]), "r"(b0), "r"(b1));
}
__device__ __forceinline__ void ldm_x4_t(uint32_t& r0, uint32_t& r1, uint32_t& r2, uint32_t& r3,
                                         uint32_t addr) {
    asm volatile("ldmatrix.sync.aligned.m8n8.x4.trans.shared.b16 {%0,%1,%2,%3}, [%4];"
                 : "=r"(r0), "=r"(r1), "=r"(r2), "=r"(r3) : "r"(addr));
}
__device__ __forceinline__ uint32_t smem_u32p(const void* p) {
    uint32_t a;
    asm("{ .reg .u64 t; cvta.to.shared.u64 t, %1; cvt.u32.u64 %0, t; }" : "=r"(a) : "l"(p));
    return a;
}

// Fast exp on the FMA pipe
__device__ __forceinline__ float fexp(float x) {
    x = fmaxf(x, -80.0f);
    float z = fmaf(x, 1.4426950408889634f, 12582912.0f);
    int   ni = __float_as_int(z) - 0x4B400000;
    float fn = z - 12582912.0f;
    float f  = fmaf(x, 1.4426950408889634f, -fn);
    float p = 0.0013333558f;
    p = fmaf(p, f, 0.0096181291f);
    p = fmaf(p, f, 0.0555041087f);
    p = fmaf(p, f, 0.2402265069f);
    p = fmaf(p, f, 0.6931471806f);
    p = fmaf(p, f, 1.0f);
    return __int_as_float(__float_as_int(p) + (ni << 23));
}

// ---------------- denom + lam scalars ----------------
__global__ void k_denom(const float* __restrict__ ts, const float* __restrict__ lam)
{
    float m = 1.0f;
    for (int b = 0; b < Bx; b++) {
        float d = ts[b*Lx + (Lx-1)] - ts[b*Lx + 0];
        m = fmaxf(m, d);
    }
    g_scal[0] = 1.0f / m;
    g_scal[1] = -fabsf(lam[0]);
}

// ---------------- temporal bias precompute ----------------
__global__ __launch_bounds__(256) void k_bias(const float* __restrict__ ts)
{
    long idx = (long)blockIdx.x * 256 + threadIdx.x;
    int  j = (int)(idx & (Lx-1));
    long t = idx >> 11;
    int  i = (int)(t & (Lx-1));
    int  b = (int)(t >> 11);
    float d = fabsf(ts[b*Lx + i] - ts[b*Lx + j]);
    g_bias[idx] = g_scal[1] * log1pf(d * g_scal[0]);
}

// ---------------- tf32 mma.sync GEMM (R6 proven version) ----------------
#define BM 128
#define BN 256
#define BK 16
#define LDA 20
#define STG_U32 ((BM + BN) * LDA)
#define GEMM_SMEM (2 * STG_U32 * 4)

template<bool SCATTER>
__global__ __launch_bounds__(256, 1) void k_gemm_mma(
    const float* __restrict__ Ain,
    const float* __restrict__ W0, const float* __restrict__ b0,
    const float* __restrict__ W1, const float* __restrict__ b1,
    const float* __restrict__ W2, const float* __restrict__ b2,
    float* __restrict__ outp)
{
    extern __shared__ uint32_t sm4[];

    const float* A;
    const float* W;
    const float* bias;
    float* out;
    if (SCATTER) {
        A = Ain;
        if (blockIdx.z == 0)      { W = W0; bias = b0; out = g_Q; }
        else if (blockIdx.z == 1) { W = W1; bias = b1; out = g_K; }
        else                      { W = W2; bias = b2; out = g_V; }
    } else {
        A = g_attn; W = W0; bias = b0; out = outp;
    }

    const int tid = threadIdx.x;
    const int wid = tid >> 5;
    const int lane = tid & 31;
    const int wm = wid >> 2;
    const int wn = wid & 3;
    const int lr = lane >> 2;
    const int lc = lane & 3;

    const int m0 = blockIdx.y * BM;
    const int n0 = blockIdx.x * BN;

    float c[4][8][4];
#pragma unroll
    for (int i = 0; i < 4; i++)
#pragma unroll
        for (int j = 0; j < 8; j++)
#pragma unroll
            for (int q = 0; q < 4; q++) c[i][j][q] = 0.f;

    float4 pa[2], pb[4];

    auto gload = [&](int k0) {
#pragma unroll
        for (int t = 0; t < 2; t++) {
            int i = tid + t * 256;
            int row = i >> 2, q = i & 3;
            pa[t] = *(const float4*)(A + (size_t)(m0 + row) * Dx + k0 + q * 4);
        }
#pragma unroll
        for (int t = 0; t < 4; t++) {
            int i = tid + t * 256;
            int row = i >> 2, q = i & 3;
            pb[t] = *(const float4*)(W + (size_t)(n0 + row) * Dx + k0 + q * 4);
        }
    };
    auto sstore = [&](int buf) {
        uint32_t* As = sm4 + buf * STG_U32;
        uint32_t* Bs = As + BM * LDA;
#pragma unroll
        for (int t = 0; t < 2; t++) {
            int i = tid + t * 256;
            int row = i >> 2, q = i & 3;
            uint32_t* p = As + row * LDA + q * 4;
            p[0] = to_tf32(pa[t].x); p[1] = to_tf32(pa[t].y);
            p[2] = to_tf32(pa[t].z); p[3] = to_tf32(pa[t].w);
        }
#pragma unroll
        for (int t = 0; t < 4; t++) {
            int i = tid + t * 256;
            int row = i >> 2, q = i & 3;
            uint32_t* p = Bs + row * LDA + q * 4;
            p[0] = to_tf32(pb[t].x); p[1] = to_tf32(pb[t].y);
            p[2] = to_tf32(pb[t].z); p[3] = to_tf32(pb[t].w);
        }
    };

    gload(0);
    sstore(0);
    __syncthreads();

    const int NITER = Dx / BK;
    for (int it = 0; it < NITER; ++it) {
        const int buf = it & 1;
        if (it + 1 < NITER) gload((it + 1) * BK);

        const uint32_t* As = sm4 + buf * STG_U32;
        const uint32_t* Bs = As + BM * LDA;
        const int mbase = wm * 64;
        const int nbase = wn * 64;
#pragma unroll
        for (int ks = 0; ks < 2; ks++) {
            const int k = ks * 8;
            uint32_t af[4][4], bf[8][2];
#pragma unroll
            for (int mt = 0; mt < 4; mt++) {
                const uint32_t* p = As + (mbase + mt * 16 + lr) * LDA + k + lc;
                af[mt][0] = p[0];
                af[mt][2] = p[4];
                af[mt][1] = p[8 * LDA];
                af[mt][3] = p[8 * LDA + 4];
            }
#pragma unroll
            for (int nt = 0; nt < 8; nt++) {
                const uint32_t* p = Bs + (nbase + nt * 8 + lr) * LDA + k + lc;
                bf[nt][0] = p[0];
                bf[nt][1] = p[4];
            }
#pragma unroll
            for (int mt = 0; mt < 4; mt++)
#pragma unroll
                for (int nt = 0; nt < 8; nt++)
                    mma16n8k8(c[mt][nt], af[mt], bf[nt]);
        }
        __syncthreads();
        if (it + 1 < NITER) {
            sstore((it + 1) & 1);
            __syncthreads();
        }
    }

#pragma unroll
    for (int mt = 0; mt < 4; mt++) {
        const int mA = m0 + wm * 64 + mt * 16 + lr;
        const int mB = mA + 8;
#pragma unroll
        for (int nt = 0; nt < 8; nt++) {
            const int n = n0 + wn * 64 + nt * 8 + 2 * lc;
            const float bn0 = bias[n], bn1 = bias[n + 1];
            float2 v0 = make_float2(c[mt][nt][0] + bn0, c[mt][nt][1] + bn1);
            float2 v1 = make_float2(c[mt][nt][2] + bn0, c[mt][nt][3] + bn1);
            if (SCATTER) {
                const int h = n >> 6, dk = n & 63;
                const int bA = mA >> 11, lA = mA & (Lx - 1);
                const int bB = mB >> 11, lB = mB & (Lx - 1);
                *(float2*)(out + (((size_t)bA*Hx + h)*Lx + lA)*DKx + dk) = v0;
                *(float2*)(out + (((size_t)bB*Hx + h)*Lx + lB)*DKx + dk) = v1;
            } else {
                *(float2*)(out + (size_t)mA * Dx + n) = v0;
                *(float2*)(out + (size_t)mB * Dx + n) = v1;
            }
        }
    }
}

// ---------------- mma.sync flash attention ----------------
// 128 threads (4 warps), BM=64 queries, key tiles of 64.
// S = 3x bf16 (Qh/Ql regs x Kh/Kl smem). PV: P packed to bf16 hi/lo IN REGISTERS
// (C-frag layout == A-frag layout), V staged bf16 hi/lo + ldmatrix.x4.trans.
// smem (u32 units): Kh[64][36] | Kl[64][36] | Vh[64*36] | Vl[64*36]
#define AO_KH 0
#define AO_KL 2304
#define AO_VH 4608
#define AO_VL 6912
#define ATTN_SMEM (9216 * 4)           // 36864 bytes

__global__ __launch_bounds__(128, 3) void k_attn_mma()
{
    extern __shared__ uint32_t smu[];
    uint32_t* KhU = smu + AO_KH;
    uint32_t* KlU = smu + AO_KL;
    uint32_t* VhU = smu + AO_VH;
    uint32_t* VlU = smu + AO_VL;

    const int tid = threadIdx.x;
    const int wid = tid >> 5, lane = tid & 31;
    const int lr = lane >> 2, lc = lane & 3;
    const int qt = gridDim.x - 1 - blockIdx.x;
    const int bh = blockIdx.y;
    const int b = bh >> 4, h = bh & 15;
    const int qi0 = qt * 64;
    const int r0 = wid * 16;
    const int qrA = qi0 + r0 + lr;
    const int qrB = qrA + 8;

    // trans-ldmatrix per-lane address offsets (V is b16 row-major, stride 72 b16 = 144B)
    const int vrow = (lane & 7) + (((lane >> 3) & 1) << 3);   // 0..15
    const int vcol = ((lane >> 4) << 3);                      // 0 or 8 (dims)
    const uint32_t sbVh = smem_u32p(VhU) + vrow * 144 + vcol * 2;
    const uint32_t sbVl = smem_u32p(VlU) + vrow * 144 + vcol * 2;

    const float* Qg = g_Q + (size_t)bh*Lx*DKx;
    const float* Kg = g_K + (size_t)bh*Lx*DKx;
    const float* Vg = g_V + (size_t)bh*Lx*DKx;
    const float* biasB = g_bias + (size_t)b*Lx*Lx;

    // Q fragments (bf16 hi/lo) in registers for the whole kernel
    uint32_t qH[4][4], qL[4][4];
#pragma unroll
    for (int ks = 0; ks < 4; ks++) {
        const int kb = 16 * ks + 2 * lc;
        float2 v;
        v = *(const float2*)(Qg + (size_t)qrA * DKx + kb);
        split2(v, qH[ks][0], qL[ks][0]);
        v = *(const float2*)(Qg + (size_t)qrB * DKx + kb);
        split2(v, qH[ks][1], qL[ks][1]);
        v = *(const float2*)(Qg + (size_t)qrA * DKx + kb + 8);
        split2(v, qH[ks][2], qL[ks][2]);
        v = *(const float2*)(Qg + (size_t)qrB * DKx + kb + 8);
        split2(v, qH[ks][3], qL[ks][3]);
    }

    float cO[8][4];
#pragma unroll
    for (int nt = 0; nt < 8; nt++)
#pragma unroll
        for (int q = 0; q < 4; q++) cO[nt][q] = 0.f;
    float mA = -1e30f, mB = -1e30f, lA = 0.f, lB = 0.f;

    const int nkt = qt + 1;

    for (int kt = 0; kt < nkt; kt++) {
        const int kj0 = kt * 64;
        __syncthreads();       // protect K/V staging from previous iteration readers

        // ---- stage K (bf16 hi/lo, u32-pair layout) and V (bf16 hi/lo, b16 row-major) ----
#pragma unroll
        for (int t = 0; t < 8; t++) {
            int i = tid + t * 128;            // 0..1023 float4 units
            int row = i >> 4, c4 = i & 15;
            float4 kv = *(const float4*)(Kg + (size_t)(kj0 + row) * DKx + c4 * 4);
            uint32_t h0, l0, h1, l1;
            split2(make_float2(kv.x, kv.y), h0, l0);
            split2(make_float2(kv.z, kv.w), h1, l1);
            KhU[row * 36 + c4 * 2]     = h0;
            KhU[row * 36 + c4 * 2 + 1] = h1;
            KlU[row * 36 + c4 * 2]     = l0;
            KlU[row * 36 + c4 * 2 + 1] = l1;
            float4 vv = *(const float4*)(Vg + (size_t)(kj0 + row) * DKx + c4 * 4);
            split2(make_float2(vv.x, vv.y), h0, l0);
            split2(make_float2(vv.z, vv.w), h1, l1);
            VhU[row * 36 + c4 * 2]     = h0;
            VhU[row * 36 + c4 * 2 + 1] = h1;
            VlU[row * 36 + c4 * 2]     = l0;
            VlU[row * 36 + c4 * 2 + 1] = l1;
        }
        __syncthreads();

        // ---- S = Q K^T : 3x bf16 ----
        float cS[8][4];
#pragma unroll
        for (int nt = 0; nt < 8; nt++)
#pragma unroll
            for (int q = 0; q < 4; q++) cS[nt][q] = 0.f;

#pragma unroll
        for (int ks = 0; ks < 4; ks++) {
#pragma unroll
            for (int nt = 0; nt < 8; nt++) {
                const uint32_t* ph = KhU + (nt * 8 + lr) * 36 + ks * 8 + lc;
                const uint32_t* pl = KlU + (nt * 8 + lr) * 36 + ks * 8 + lc;
                uint32_t bH0 = ph[0], bH1 = ph[4];
                uint32_t bL0 = pl[0], bL1 = pl[4];
                mma_bf16(cS[nt], qH[ks], bH0, bH1);
                mma_bf16(cS[nt], qH[ks], bL0, bL1);
                mma_bf16(cS[nt], qL[ks], bH0, bH1);
            }
        }

        // ---- bias + causal mask + online softmax ----
        const bool domask = (kt == qt);
        float rmA = -1e30f, rmB = -1e30f;
#pragma unroll
        for (int nt = 0; nt < 8; nt++) {
            const int kc = kj0 + nt * 8 + 2 * lc;
            float2 biA = *(const float2*)(biasB + (size_t)qrA * Lx + kc);
            float2 biB = *(const float2*)(biasB + (size_t)qrB * Lx + kc);
            float v0 = fmaf(cS[nt][0], 0.125f, biA.x);
            float v1 = fmaf(cS[nt][1], 0.125f, biA.y);
            float v2 = fmaf(cS[nt][2], 0.125f, biB.x);
            float v3 = fmaf(cS[nt][3], 0.125f, biB.y);
            if (domask) {
                if (kc     > qrA) v0 = -1e30f;
                if (kc + 1 > qrA) v1 = -1e30f;
                if (kc     > qrB) v2 = -1e30f;
                if (kc + 1 > qrB) v3 = -1e30f;
            }
            cS[nt][0] = v0; cS[nt][1] = v1; cS[nt][2] = v2; cS[nt][3] = v3;
            rmA = fmaxf(rmA, fmaxf(v0, v1));
            rmB = fmaxf(rmB, fmaxf(v2, v3));
        }
        rmA = fmaxf(rmA, __shfl_xor_sync(0xffffffffu, rmA, 1));
        rmA = fmaxf(rmA, __shfl_xor_sync(0xffffffffu, rmA, 2));
        rmB = fmaxf(rmB, __shfl_xor_sync(0xffffffffu, rmB, 1));
        rmB = fmaxf(rmB, __shfl_xor_sync(0xffffffffu, rmB, 2));

        const float mnA = fmaxf(mA, rmA);
        const float mnB = fmaxf(mB, rmB);
        const float scA = fexp(mA - mnA);
        const float scB = fexp(mB - mnB);
        mA = mnA; mB = mnB;

        float rsA = 0.f, rsB = 0.f;
#pragma unroll
        for (int nt = 0; nt < 8; nt++) {
            float p0 = fexp(cS[nt][0] - mnA);
            float p1 = fexp(cS[nt][1] - mnA);
            float p2 = fexp(cS[nt][2] - mnB);
            float p3 = fexp(cS[nt][3] - mnB);
            rsA += p0 + p1;
            rsB += p2 + p3;
            cS[nt][0] = p0; cS[nt][1] = p1; cS[nt][2] = p2; cS[nt][3] = p3;
        }
        rsA += __shfl_xor_sync(0xffffffffu, rsA, 1);
        rsA += __shfl_xor_sync(0xffffffffu, rsA, 2);
        rsB += __shfl_xor_sync(0xffffffffu, rsB, 1);
        rsB += __shfl_xor_sync(0xffffffffu, rsB, 2);
        lA = lA * scA + rsA;
        lB = lB * scB + rsB;
#pragma unroll
        for (int nt = 0; nt < 8; nt++) {
            cO[nt][0] *= scA; cO[nt][1] *= scA;
            cO[nt][2] *= scB; cO[nt][3] *= scB;
        }

        // ---- P -> bf16 hi/lo A-fragments (in registers; C-frag layout == A-frag layout) ----
        uint32_t aPh[4][4], aPl[4][4];
#pragma unroll
        for (int nt2 = 0; nt2 < 4; nt2++) {
            split2(make_float2(cS[2*nt2][0],   cS[2*nt2][1]),   aPh[nt2][0], aPl[nt2][0]);
            split2(make_float2(cS[2*nt2][2],   cS[2*nt2][3]),   aPh[nt2][1], aPl[nt2][1]);
            split2(make_float2(cS[2*nt2+1][0], cS[2*nt2+1][1]), aPh[nt2][2], aPl[nt2][2]);
            split2(make_float2(cS[2*nt2+1][2], cS[2*nt2+1][3]), aPh[nt2][3], aPl[nt2][3]);
        }

        // ---- O += P @ V : PhVh + PlVh + PhVl, V frags via ldmatrix.trans ----
#pragma unroll
        for (int nt2 = 0; nt2 < 4; nt2++) {
            const uint32_t ko = nt2 * 16 * 144;     // 16 key rows per step
#pragma unroll
            for (int dp = 0; dp < 4; dp++) {
                const uint32_t doff = ko + dp * 32;  // 16 dims = 32 bytes
                uint32_t h0, h1, h2, h3;
                ldm_x4_t(h0, h1, h2, h3, sbVh + doff);
                mma_bf16(cO[2*dp],     aPh[nt2], h0, h1);
                mma_bf16(cO[2*dp + 1], aPh[nt2], h2, h3);
                mma_bf16(cO[2*dp],     aPl[nt2], h0, h1);
                mma_bf16(cO[2*dp + 1], aPl[nt2], h2, h3);
                uint32_t l0, l1, l2, l3;
                ldm_x4_t(l0, l1, l2, l3, sbVl + doff);
                mma_bf16(cO[2*dp],     aPh[nt2], l0, l1);
                mma_bf16(cO[2*dp + 1], aPh[nt2], l2, l3);
            }
        }
    }

    // ---- normalize + write to g_attn [B,L,H*DK] ----
    const float invA = 1.0f / lA;
    const float invB = 1.0f / lB;
    float* oA = g_attn + ((size_t)b * Lx + qrA) * Dx + h * DKx;
    float* oB = g_attn + ((size_t)b * Lx + qrB) * Dx + h * DKx;
#pragma unroll
    for (int nt = 0; nt < 8; nt++) {
        const int n = nt * 8 + 2 * lc;
        *(float2*)(oA + n) = make_float2(cO[nt][0] * invA, cO[nt][1] * invA);
        *(float2*)(oB + n) = make_float2(cO[nt][2] * invB, cO[nt][3] * invB);
    }
}

// ---------------- launch ----------------
extern "C" void kernel_launch(void* const* d_in, const int* in_sizes, int n_in,
                              void* d_out, int out_size)
{
    const float* x   = (const float*)d_in[0];
    const float* ts  = (const float*)d_in[1];
    const float* Wq  = (const float*)d_in[4];
    const float* bq  = (const float*)d_in[5];
    const float* Wk  = (const float*)d_in[6];
    const float* bk  = (const float*)d_in[7];
    const float* Wv  = (const float*)d_in[8];
    const float* bv  = (const float*)d_in[9];
    const float* Wo  = (const float*)d_in[10];
    const float* bo  = (const float*)d_in[11];
    const float* lam = (const float*)d_in[12];
    float* out = (float*)d_out;

    k_denom<<<1, 1>>>(ts, lam);
    k_bias<<<(Bx*Lx*Lx)/256, 256>>>(ts);

    cudaFuncSetAttribute(k_gemm_mma<true>,  cudaFuncAttributeMaxDynamicSharedMemorySize, GEMM_SMEM);
    cudaFuncSetAttribute(k_gemm_mma<false>, cudaFuncAttributeMaxDynamicSharedMemorySize, GEMM_SMEM);
    cudaFuncSetAttribute(k_attn_mma, cudaFuncAttributeMaxDynamicSharedMemorySize, ATTN_SMEM);

    // Q/K/V projections
    k_gemm_mma<true><<<dim3(Dx/BN, (Bx*Lx)/BM, 3), 256, GEMM_SMEM>>>(
        x, Wq, bq, Wk, bk, Wv, bv, nullptr);

    // flash attention
    k_attn_mma<<<dim3(Lx/64, BHx), 128, ATTN_SMEM>>>();

    // output projection
    k_gemm_mma<false><<<dim3(Dx/BN, (Bx*Lx)/BM, 1), 256, GEMM_SMEM>>>(
        nullptr, Wo, bo, nullptr, nullptr, nullptr, nullptr, out);
}

// round 10
// speedup vs baseline: 1.3299x; 1.1282x over previous
#include <cuda_runtime.h>
#include <cuda_bf16.h>
#include <math.h>
#include <stdint.h>

// Problem constants
#define Bx  2
#define Lx  2048
#define Dx  1024
#define Hx  16
#define DKx 64
#define BHx (Bx*Hx)

// ---------------- device scratch (no allocations allowed) ----------------
__device__ float g_Q[(size_t)BHx*Lx*DKx];      // [B,H,L,DK]
__device__ float g_K[(size_t)BHx*Lx*DKx];
__device__ float g_V[(size_t)BHx*Lx*DKx];
__device__ float g_attn[(size_t)Bx*Lx*Dx];     // [B,L,H*DK]
__device__ float g_bias[(size_t)Bx*Lx*Lx];     // -|lam|*log1p(|ti-tj|/denom)
__device__ float g_scal[2];                    // [0]=1/denom, [1]=-|lam|
__device__ float g_xr[(size_t)4096*1024];      // tf32-rounded A operand (x, later attn-out)
__device__ float g_wr[(size_t)4*1024*1024];    // tf32-rounded weights (q,k,v,o)

// ---------------- helpers ----------------
__device__ __forceinline__ uint32_t to_tf32(float x) {
    uint32_t r;
    asm("cvt.rna.tf32.f32 %0, %1;" : "=r"(r) : "f"(x));
    return r;
}

// split two floats into packed bf16x2 hi and lo
__device__ __forceinline__ void split2(float2 v, uint32_t& hi, uint32_t& lo) {
    __nv_bfloat162 h = __floats2bfloat162_rn(v.x, v.y);
    float hx = __bfloat162float(h.x);
    float hy = __bfloat162float(h.y);
    __nv_bfloat162 l = __floats2bfloat162_rn(v.x - hx, v.y - hy);
    hi = *(uint32_t*)&h;
    lo = *(uint32_t*)&l;
}

__device__ __forceinline__ void mma16n8k8(float* c, const uint32_t* a, const uint32_t* b) {
    asm volatile(
        "mma.sync.aligned.m16n8k8.row.col.f32.tf32.tf32.f32 "
        "{%0,%1,%2,%3}, {%4,%5,%6,%7}, {%8,%9}, {%0,%1,%2,%3};"
        : "+f"(c[0]), "+f"(c[1]), "+f"(c[2]), "+f"(c[3])
        : "r"(a[0]), "r"(a[1]), "r"(a[2]), "r"(a[3]), "r"(b[0]), "r"(b[1]));
}
__device__ __forceinline__ void mma_bf16(float* c, const uint32_t* a, uint32_t b0, uint32_t b1) {
    asm volatile(
        "mma.sync.aligned.m16n8k16.row.col.f32.bf16.bf16.f32 "
        "{%0,%1,%2,%3}, {%4,%5,%6,%7}, {%8,%9}, {%0,%1,%2,%3};"
        : "+f"(c[0]), "+f"(c[1]), "+f"(c[2]), "+f"(c[3])
        : "r"(a[0]), "r"(a[1]), "r"(a[2]), "r"(a[3]), "r"(b0), "r"(b1));
}
__device__ __forceinline__ void ldm_x4(uint32_t& r0, uint32_t& r1, uint32_t& r2, uint32_t& r3,
                                       uint32_t addr) {
    asm volatile("ldmatrix.sync.aligned.m8n8.x4.shared.b16 {%0,%1,%2,%3}, [%4];"
                 : "=r"(r0), "=r"(r1), "=r"(r2), "=r"(r3) : "r"(addr));
}
__device__ __forceinline__ void ldm_x4_t(uint32_t& r0, uint32_t& r1, uint32_t& r2, uint32_t& r3,
                                         uint32_t addr) {
    asm volatile("ldmatrix.sync.aligned.m8n8.x4.trans.shared.b16 {%0,%1,%2,%3}, [%4];"
                 : "=r"(r0), "=r"(r1), "=r"(r2), "=r"(r3) : "r"(addr));
}
__device__ __forceinline__ void cpasync16(uint32_t s, const void* g) {
    asm volatile("cp.async.cg.shared.global [%0], [%1], 16;" :: "r"(s), "l"(g));
}
__device__ __forceinline__ uint32_t smem_u32p(const void* p) {
    uint32_t a;
    asm("{ .reg .u64 t; cvta.to.shared.u64 t, %1; cvt.u32.u64 %0, t; }" : "=r"(a) : "l"(p));
    return a;
}

// Fast exp on the FMA pipe
__device__ __forceinline__ float fexp(float x) {
    x = fmaxf(x, -80.0f);
    float z = fmaf(x, 1.4426950408889634f, 12582912.0f);
    int   ni = __float_as_int(z) - 0x4B400000;
    float fn = z - 12582912.0f;
    float f  = fmaf(x, 1.4426950408889634f, -fn);
    float p = 0.0013333558f;
    p = fmaf(p, f, 0.0096181291f);
    p = fmaf(p, f, 0.0555041087f);
    p = fmaf(p, f, 0.2402265069f);
    p = fmaf(p, f, 0.6931471806f);
    p = fmaf(p, f, 1.0f);
    return __int_as_float(__float_as_int(p) + (ni << 23));
}

// ---------------- denom + lam scalars ----------------
__global__ void k_denom(const float* __restrict__ ts, const float* __restrict__ lam)
{
    float m = 1.0f;
    for (int b = 0; b < Bx; b++) {
        float d = ts[b*Lx + (Lx-1)] - ts[b*Lx + 0];
        m = fmaxf(m, d);
    }
    g_scal[0] = 1.0f / m;
    g_scal[1] = -fabsf(lam[0]);
}

// ---------------- temporal bias precompute ----------------
__global__ __launch_bounds__(256) void k_bias(const float* __restrict__ ts)
{
    long idx = (long)blockIdx.x * 256 + threadIdx.x;
    int  j = (int)(idx & (Lx-1));
    long t = idx >> 11;
    int  i = (int)(t & (Lx-1));
    int  b = (int)(t >> 11);
    float d = fabsf(ts[b*Lx + i] - ts[b*Lx + j]);
    g_bias[idx] = g_scal[1] * log1pf(d * g_scal[0]);
}

// ---------------- tf32 pre-rounding passes ----------------
__global__ __launch_bounds__(256) void k_cvt(const float* __restrict__ s,
                                             float* __restrict__ d)
{
    size_t i = ((size_t)blockIdx.x * 256 + threadIdx.x) * 4;
    float4 v = *(const float4*)(s + i);
    v.x = __uint_as_float(to_tf32(v.x));
    v.y = __uint_as_float(to_tf32(v.y));
    v.z = __uint_as_float(to_tf32(v.z));
    v.w = __uint_as_float(to_tf32(v.w));
    *(float4*)(d + i) = v;
}
__global__ __launch_bounds__(256) void k_cvtw(const float* __restrict__ w0,
                                              const float* __restrict__ w1,
                                              const float* __restrict__ w2,
                                              const float* __restrict__ w3)
{
    const float* s = (blockIdx.z == 0) ? w0 : (blockIdx.z == 1) ? w1 :
                     (blockIdx.z == 2) ? w2 : w3;
    float* d = g_wr + (size_t)blockIdx.z * 1024 * 1024;
    size_t i = ((size_t)blockIdx.x * 256 + threadIdx.x) * 4;
    float4 v = *(const float4*)(s + i);
    v.x = __uint_as_float(to_tf32(v.x));
    v.y = __uint_as_float(to_tf32(v.y));
    v.z = __uint_as_float(to_tf32(v.z));
    v.w = __uint_as_float(to_tf32(v.w));
    *(float4*)(d + i) = v;
}

// ---------------- tf32 GEMM: cp.async staging + ldmatrix frags ----------------
// out[m,n] = sum_k A[m,k]*W[n,k] + bias[n];  A,W pre-rounded to tf32 in gmem.
// BM=128, BN=256, BK=32. 256 threads = 8 warps (2m x 4n), warp tile 64x64.
#define BM 128
#define BN 256
#define BK 32
#define LDA 36                         // padded row stride in u32 (32 data + 4 pad)
#define STG_U32 ((BM + BN) * LDA)      // 13824 u32 per stage
#define GEMM_SMEM (2 * STG_U32 * 4)    // 110592 B

template<bool SCATTER>
__global__ __launch_bounds__(256, 1) void k_gemm_tc(
    const float* __restrict__ b0, const float* __restrict__ b1,
    const float* __restrict__ b2, float* __restrict__ outp)
{
    extern __shared__ uint32_t smu[];
    const uint32_t sb = smem_u32p(smu);

    const float* bias;
    float* out;
    int widx;
    if (SCATTER) {
        widx = blockIdx.z;
        if (widx == 0)      { bias = b0; out = g_Q; }
        else if (widx == 1) { bias = b1; out = g_K; }
        else                { bias = b2; out = g_V; }
    } else {
        widx = 3; bias = b0; out = outp;
    }
    const float* A = g_xr;
    const float* W = g_wr + (size_t)widx * 1024 * 1024;

    const int tid = threadIdx.x;
    const int wid = tid >> 5, lane = tid & 31;
    const int wm = wid >> 2, wn = wid & 3;
    const int lr = lane >> 2, lc = lane & 3;
    const int m0 = blockIdx.y * BM;
    const int n0 = blockIdx.x * BN;

    float c[4][8][4];
#pragma unroll
    for (int i = 0; i < 4; i++)
#pragma unroll
        for (int j = 0; j < 8; j++)
#pragma unroll
            for (int q = 0; q < 4; q++) c[i][j][q] = 0.f;

    // ldmatrix per-lane offsets (bytes, relative to stage base)
    const int g = lane >> 3, s = lane & 7;
    const uint32_t aoff = ((wm * 64 + ((g & 1) << 3) + s) * LDA + (g >> 1) * 4) * 4;
    const uint32_t boff = (BM * LDA + (wn * 64 + ((g >> 1) << 3) + s) * LDA + (g & 1) * 4) * 4;

    auto load_stage = [&](int st, int k0) {
        const uint32_t base = sb + st * STG_U32 * 4;
        // A: 128 rows x 8 chunks of 16B = 1024 chunks, 4 passes
#pragma unroll
        for (int t = 0; t < 4; t++) {
            int i = tid + t * 256;
            int r = i >> 3, q = i & 7;
            cpasync16(base + (r * LDA + q * 4) * 4, A + (size_t)(m0 + r) * Dx + k0 + q * 4);
        }
        // B: 256 rows x 8 chunks = 2048 chunks, 8 passes
#pragma unroll
        for (int t = 0; t < 8; t++) {
            int i = tid + t * 256;
            int r = i >> 3, q = i & 7;
            cpasync16(base + (BM * LDA + r * LDA + q * 4) * 4,
                      W + (size_t)(n0 + r) * Dx + k0 + q * 4);
        }
        asm volatile("cp.async.commit_group;");
    };

    load_stage(0, 0);

    const int NITER = Dx / BK;               // 32
    for (int it = 0; it < NITER; ++it) {
        const int buf = it & 1;
        if (it + 1 < NITER) {
            load_stage((it + 1) & 1, (it + 1) * BK);
            asm volatile("cp.async.wait_group 1;");
        } else {
            asm volatile("cp.async.wait_group 0;");
        }
        __syncthreads();

        const uint32_t base = sb + buf * STG_U32 * 4;
#pragma unroll
        for (int ks = 0; ks < 4; ks++) {
            const uint32_t ko = ks * 32;     // 8 floats per ks
            uint32_t af[4][4], bf[8][2];
#pragma unroll
            for (int mt = 0; mt < 4; mt++)
                ldm_x4(af[mt][0], af[mt][1], af[mt][2], af[mt][3],
                       base + aoff + mt * 16 * LDA * 4 + ko);
#pragma unroll
            for (int np = 0; np < 4; np++) {
                uint32_t r0, r1, r2, r3;
                ldm_x4(r0, r1, r2, r3, base + boff + np * 16 * LDA * 4 + ko);
                bf[2*np][0] = r0; bf[2*np][1] = r1;
                bf[2*np+1][0] = r2; bf[2*np+1][1] = r3;
            }
#pragma unroll
            for (int mt = 0; mt < 4; mt++)
#pragma unroll
                for (int nt = 0; nt < 8; nt++)
                    mma16n8k8(c[mt][nt], af[mt], bf[nt]);
        }
        __syncthreads();
    }

    // epilogue: add bias, store
#pragma unroll
    for (int mt = 0; mt < 4; mt++) {
        const int mA = m0 + wm * 64 + mt * 16 + lr;
        const int mB = mA + 8;
#pragma unroll
        for (int nt = 0; nt < 8; nt++) {
            const int n = n0 + wn * 64 + nt * 8 + 2 * lc;
            const float bn0 = bias[n], bn1 = bias[n + 1];
            float2 v0 = make_float2(c[mt][nt][0] + bn0, c[mt][nt][1] + bn1);
            float2 v1 = make_float2(c[mt][nt][2] + bn0, c[mt][nt][3] + bn1);
            if (SCATTER) {
                const int h = n >> 6, dk = n & 63;
                const int bA = mA >> 11, lA = mA & (Lx - 1);
                const int bB = mB >> 11, lB = mB & (Lx - 1);
                *(float2*)(out + (((size_t)bA*Hx + h)*Lx + lA)*DKx + dk) = v0;
                *(float2*)(out + (((size_t)bB*Hx + h)*Lx + lB)*DKx + dk) = v1;
            } else {
                *(float2*)(out + (size_t)mA * Dx + n) = v0;
                *(float2*)(out + (size_t)mB * Dx + n) = v1;
            }
        }
    }
}

// ---------------- mma.sync flash attention (unchanged from R9) ----------------
#define AO_KH 0
#define AO_KL 2304
#define AO_VH 4608
#define AO_VL 6912
#define ATTN_SMEM (9216 * 4)           // 36864 bytes

__global__ __launch_bounds__(128, 3) void k_attn_mma()
{
    extern __shared__ uint32_t smu[];
    uint32_t* KhU = smu + AO_KH;
    uint32_t* KlU = smu + AO_KL;
    uint32_t* VhU = smu + AO_VH;
    uint32_t* VlU = smu + AO_VL;

    const int tid = threadIdx.x;
    const int wid = tid >> 5, lane = tid & 31;
    const int lr = lane >> 2, lc = lane & 3;
    const int qt = gridDim.x - 1 - blockIdx.x;
    const int bh = blockIdx.y;
    const int b = bh >> 4, h = bh & 15;
    const int qi0 = qt * 64;
    const int r0 = wid * 16;
    const int qrA = qi0 + r0 + lr;
    const int qrB = qrA + 8;

    const int vrow = (lane & 7) + (((lane >> 3) & 1) << 3);
    const int vcol = ((lane >> 4) << 3);
    const uint32_t sbVh = smem_u32p(VhU) + vrow * 144 + vcol * 2;
    const uint32_t sbVl = smem_u32p(VlU) + vrow * 144 + vcol * 2;

    const float* Qg = g_Q + (size_t)bh*Lx*DKx;
    const float* Kg = g_K + (size_t)bh*Lx*DKx;
    const float* Vg = g_V + (size_t)bh*Lx*DKx;
    const float* biasB = g_bias + (size_t)b*Lx*Lx;

    uint32_t qH[4][4], qL[4][4];
#pragma unroll
    for (int ks = 0; ks < 4; ks++) {
        const int kb = 16 * ks + 2 * lc;
        float2 v;
        v = *(const float2*)(Qg + (size_t)qrA * DKx + kb);
        split2(v, qH[ks][0], qL[ks][0]);
        v = *(const float2*)(Qg + (size_t)qrB * DKx + kb);
        split2(v, qH[ks][1], qL[ks][1]);
        v = *(const float2*)(Qg + (size_t)qrA * DKx + kb + 8);
        split2(v, qH[ks][2], qL[ks][2]);
        v = *(const float2*)(Qg + (size_t)qrB * DKx + kb + 8);
        split2(v, qH[ks][3], qL[ks][3]);
    }

    float cO[8][4];
#pragma unroll
    for (int nt = 0; nt < 8; nt++)
#pragma unroll
        for (int q = 0; q < 4; q++) cO[nt][q] = 0.f;
    float mA = -1e30f, mB = -1e30f, lA = 0.f, lB = 0.f;

    const int nkt = qt + 1;

    for (int kt = 0; kt < nkt; kt++) {
        const int kj0 = kt * 64;
        __syncthreads();

#pragma unroll
        for (int t = 0; t < 8; t++) {
            int i = tid + t * 128;
            int row = i >> 4, c4 = i & 15;
            float4 kv = *(const float4*)(Kg + (size_t)(kj0 + row) * DKx + c4 * 4);
            uint32_t h0, l0, h1, l1;
            split2(make_float2(kv.x, kv.y), h0, l0);
            split2(make_float2(kv.z, kv.w), h1, l1);
            KhU[row * 36 + c4 * 2]     = h0;
            KhU[row * 36 + c4 * 2 + 1] = h1;
            KlU[row * 36 + c4 * 2]     = l0;
            KlU[row * 36 + c4 * 2 + 1] = l1;
            float4 vv = *(const float4*)(Vg + (size_t)(kj0 + row) * DKx + c4 * 4);
            split2(make_float2(vv.x, vv.y), h0, l0);
            split2(make_float2(vv.z, vv.w), h1, l1);
            VhU[row * 36 + c4 * 2]     = h0;
            VhU[row * 36 + c4 * 2 + 1] = h1;
            VlU[row * 36 + c4 * 2]     = l0;
            VlU[row * 36 + c4 * 2 + 1] = l1;
        }
        __syncthreads();

        float cS[8][4];
#pragma unroll
        for (int nt = 0; nt < 8; nt++)
#pragma unroll
            for (int q = 0; q < 4; q++) cS[nt][q] = 0.f;

#pragma unroll
        for (int ks = 0; ks < 4; ks++) {
#pragma unroll
            for (int nt = 0; nt < 8; nt++) {
                const uint32_t* ph = KhU + (nt * 8 + lr) * 36 + ks * 8 + lc;
                const uint32_t* pl = KlU + (nt * 8 + lr) * 36 + ks * 8 + lc;
                uint32_t bH0 = ph[0], bH1 = ph[4];
                uint32_t bL0 = pl[0], bL1 = pl[4];
                mma_bf16(cS[nt], qH[ks], bH0, bH1);
                mma_bf16(cS[nt], qH[ks], bL0, bL1);
                mma_bf16(cS[nt], qL[ks], bH0, bH1);
            }
        }

        const bool domask = (kt == qt);
        float rmA = -1e30f, rmB = -1e30f;
#pragma unroll
        for (int nt = 0; nt < 8; nt++) {
            const int kc = kj0 + nt * 8 + 2 * lc;
            float2 biA = *(const float2*)(biasB + (size_t)qrA * Lx + kc);
            float2 biB = *(const float2*)(biasB + (size_t)qrB * Lx + kc);
            float v0 = fmaf(cS[nt][0], 0.125f, biA.x);
            float v1 = fmaf(cS[nt][1], 0.125f, biA.y);
            float v2 = fmaf(cS[nt][2], 0.125f, biB.x);
            float v3 = fmaf(cS[nt][3], 0.125f, biB.y);
            if (domask) {
                if (kc     > qrA) v0 = -1e30f;
                if (kc + 1 > qrA) v1 = -1e30f;
                if (kc     > qrB) v2 = -1e30f;
                if (kc + 1 > qrB) v3 = -1e30f;
            }
            cS[nt][0] = v0; cS[nt][1] = v1; cS[nt][2] = v2; cS[nt][3] = v3;
            rmA = fmaxf(rmA, fmaxf(v0, v1));
            rmB = fmaxf(rmB, fmaxf(v2, v3));
        }
        rmA = fmaxf(rmA, __shfl_xor_sync(0xffffffffu, rmA, 1));
        rmA = fmaxf(rmA, __shfl_xor_sync(0xffffffffu, rmA, 2));
        rmB = fmaxf(rmB, __shfl_xor_sync(0xffffffffu, rmB, 1));
        rmB = fmaxf(rmB, __shfl_xor_sync(0xffffffffu, rmB, 2));

        const float mnA = fmaxf(mA, rmA);
        const float mnB = fmaxf(mB, rmB);
        const float scA = fexp(mA - mnA);
        const float scB = fexp(mB - mnB);
        mA = mnA; mB = mnB;

        float rsA = 0.f, rsB = 0.f;
#pragma unroll
        for (int nt = 0; nt < 8; nt++) {
            float p0 = fexp(cS[nt][0] - mnA);
            float p1 = fexp(cS[nt][1] - mnA);
            float p2 = fexp(cS[nt][2] - mnB);
            float p3 = fexp(cS[nt][3] - mnB);
            rsA += p0 + p1;
            rsB += p2 + p3;
            cS[nt][0] = p0; cS[nt][1] = p1; cS[nt][2] = p2; cS[nt][3] = p3;
        }
        rsA += __shfl_xor_sync(0xffffffffu, rsA, 1);
        rsA += __shfl_xor_sync(0xffffffffu, rsA, 2);
        rsB += __shfl_xor_sync(0xffffffffu, rsB, 1);
        rsB += __shfl_xor_sync(0xffffffffu, rsB, 2);
        lA = lA * scA + rsA;
        lB = lB * scB + rsB;
#pragma unroll
        for (int nt = 0; nt < 8; nt++) {
            cO[nt][0] *= scA; cO[nt][1] *= scA;
            cO[nt][2] *= scB; cO[nt][3] *= scB;
        }

        uint32_t aPh[4][4], aPl[4][4];
#pragma unroll
        for (int nt2 = 0; nt2 < 4; nt2++) {
            split2(make_float2(cS[2*nt2][0],   cS[2*nt2][1]),   aPh[nt2][0], aPl[nt2][0]);
            split2(make_float2(cS[2*nt2][2],   cS[2*nt2][3]),   aPh[nt2][1], aPl[nt2][1]);
            split2(make_float2(cS[2*nt2+1][0], cS[2*nt2+1][1]), aPh[nt2][2], aPl[nt2][2]);
            split2(make_float2(cS[2*nt2+1][2], cS[2*nt2+1][3]), aPh[nt2][3], aPl[nt2][3]);
        }

#pragma unroll
        for (int nt2 = 0; nt2 < 4; nt2++) {
            const uint32_t ko = nt2 * 16 * 144;
#pragma unroll
            for (int dp = 0; dp < 4; dp++) {
                const uint32_t doff = ko + dp * 32;
                uint32_t h0, h1, h2, h3;
                ldm_x4_t(h0, h1, h2, h3, sbVh + doff);
                mma_bf16(cO[2*dp],     aPh[nt2], h0, h1);
                mma_bf16(cO[2*dp + 1], aPh[nt2], h2, h3);
                mma_bf16(cO[2*dp],     aPl[nt2], h0, h1);
                mma_bf16(cO[2*dp + 1], aPl[nt2], h2, h3);
                uint32_t l0, l1, l2, l3;
                ldm_x4_t(l0, l1, l2, l3, sbVl + doff);
                mma_bf16(cO[2*dp],     aPh[nt2], l0, l1);
                mma_bf16(cO[2*dp + 1], aPh[nt2], l2, l3);
            }
        }
    }

    const float invA = 1.0f / lA;
    const float invB = 1.0f / lB;
    float* oA = g_attn + ((size_t)b * Lx + qrA) * Dx + h * DKx;
    float* oB = g_attn + ((size_t)b * Lx + qrB) * Dx + h * DKx;
#pragma unroll
    for (int nt = 0; nt < 8; nt++) {
        const int n = nt * 8 + 2 * lc;
        *(float2*)(oA + n) = make_float2(cO[nt][0] * invA, cO[nt][1] * invA);
        *(float2*)(oB + n) = make_float2(cO[nt][2] * invB, cO[nt][3] * invB);
    }
}

// ---------------- launch ----------------
extern "C" void kernel_launch(void* const* d_in, const int* in_sizes, int n_in,
                              void* d_out, int out_size)
{
    const float* x   = (const float*)d_in[0];
    const float* ts  = (const float*)d_in[1];
    const float* Wq  = (const float*)d_in[4];
    const float* bq  = (const float*)d_in[5];
    const float* Wk  = (const float*)d_in[6];
    const float* bk  = (const float*)d_in[7];
    const float* Wv  = (const float*)d_in[8];
    const float* bv  = (const float*)d_in[9];
    const float* Wo  = (const float*)d_in[10];
    const float* bo  = (const float*)d_in[11];
    const float* lam = (const float*)d_in[12];
    float* out = (float*)d_out;

    float* xr_p; float* attn_p;
    cudaGetSymbolAddress((void**)&xr_p, g_xr);
    cudaGetSymbolAddress((void**)&attn_p, g_attn);

    k_denom<<<1, 1>>>(ts, lam);
    k_bias<<<(Bx*Lx*Lx)/256, 256>>>(ts);

    // tf32 pre-rounding
    k_cvt<<<(4096*1024)/1024, 256>>>(x, xr_p);
    k_cvtw<<<dim3((1024*1024)/1024, 1, 4), 256>>>(Wq, Wk, Wv, Wo);

    cudaFuncSetAttribute(k_gemm_tc<true>,  cudaFuncAttributeMaxDynamicSharedMemorySize, GEMM_SMEM);
    cudaFuncSetAttribute(k_gemm_tc<false>, cudaFuncAttributeMaxDynamicSharedMemorySize, GEMM_SMEM);
    cudaFuncSetAttribute(k_attn_mma, cudaFuncAttributeMaxDynamicSharedMemorySize, ATTN_SMEM);

    // Q/K/V projections
    k_gemm_tc<true><<<dim3(Dx/BN, (Bx*Lx)/BM, 3), 256, GEMM_SMEM>>>(
        bq, bk, bv, nullptr);

    // flash attention
    k_attn_mma<<<dim3(Lx/64, BHx), 128, ATTN_SMEM>>>();

    // round attention output, then output projection
    k_cvt<<<(4096*1024)/1024, 256>>>(attn_p, xr_p);
    k_gemm_tc<false><<<dim3(Dx/BN, (Bx*Lx)/BM, 1), 256, GEMM_SMEM>>>(
        bo, nullptr, nullptr, out);
}

// round 11
// speedup vs baseline: 1.3436x; 1.0103x over previous
#include <cuda_runtime.h>
#include <cuda_bf16.h>
#include <math.h>
#include <stdint.h>

// Problem constants
#define Bx  2
#define Lx  2048
#define Dx  1024
#define Hx  16
#define DKx 64
#define BHx (Bx*Hx)

// ---------------- device scratch (no allocations allowed) ----------------
__device__ float g_Q[(size_t)BHx*Lx*DKx];      // [B,H,L,DK]
__device__ float g_K[(size_t)BHx*Lx*DKx];
__device__ float g_V[(size_t)BHx*Lx*DKx];
__device__ float g_attn[(size_t)Bx*Lx*Dx];     // [B,L,H*DK]
__device__ float g_bias[(size_t)Bx*Lx*Lx];     // -|lam|*log1p(|ti-tj|/denom)
__device__ float g_scal[2];                    // [0]=1/denom, [1]=-|lam|
__device__ float g_xr[(size_t)4096*1024];      // tf32-rounded A operand (x, later attn-out)
__device__ float g_wr[(size_t)4*1024*1024];    // tf32-rounded weights (q,k,v,o)
// pre-packed bf16 hi/lo K,V: [bh][L][32 u32] (u32 = bf16x2 along dk)
__device__ uint32_t g_kh[(size_t)BHx*Lx*32], g_kl[(size_t)BHx*Lx*32];
__device__ uint32_t g_vh[(size_t)BHx*Lx*32], g_vl[(size_t)BHx*Lx*32];

// ---------------- helpers ----------------
__device__ __forceinline__ uint32_t to_tf32(float x) {
    uint32_t r;
    asm("cvt.rna.tf32.f32 %0, %1;" : "=r"(r) : "f"(x));
    return r;
}
__device__ __forceinline__ void split2(float2 v, uint32_t& hi, uint32_t& lo) {
    __nv_bfloat162 h = __floats2bfloat162_rn(v.x, v.y);
    float hx = __bfloat162float(h.x);
    float hy = __bfloat162float(h.y);
    __nv_bfloat162 l = __floats2bfloat162_rn(v.x - hx, v.y - hy);
    hi = *(uint32_t*)&h;
    lo = *(uint32_t*)&l;
}

__device__ __forceinline__ void mma16n8k8(float* c, const uint32_t* a, const uint32_t* b) {
    asm volatile(
        "mma.sync.aligned.m16n8k8.row.col.f32.tf32.tf32.f32 "
        "{%0,%1,%2,%3}, {%4,%5,%6,%7}, {%8,%9}, {%0,%1,%2,%3};"
        : "+f"(c[0]), "+f"(c[1]), "+f"(c[2]), "+f"(c[3])
        : "r"(a[0]), "r"(a[1]), "r"(a[2]), "r"(a[3]), "r"(b[0]), "r"(b[1]));
}
__device__ __forceinline__ void mma_bf16(float* c, const uint32_t* a, uint32_t b0, uint32_t b1) {
    asm volatile(
        "mma.sync.aligned.m16n8k16.row.col.f32.bf16.bf16.f32 "
        "{%0,%1,%2,%3}, {%4,%5,%6,%7}, {%8,%9}, {%0,%1,%2,%3};"
        : "+f"(c[0]), "+f"(c[1]), "+f"(c[2]), "+f"(c[3])
        : "r"(a[0]), "r"(a[1]), "r"(a[2]), "r"(a[3]), "r"(b0), "r"(b1));
}
__device__ __forceinline__ void ldm_x4(uint32_t& r0, uint32_t& r1, uint32_t& r2, uint32_t& r3,
                                       uint32_t addr) {
    asm volatile("ldmatrix.sync.aligned.m8n8.x4.shared.b16 {%0,%1,%2,%3}, [%4];"
                 : "=r"(r0), "=r"(r1), "=r"(r2), "=r"(r3) : "r"(addr));
}
__device__ __forceinline__ void ldm_x4_t(uint32_t& r0, uint32_t& r1, uint32_t& r2, uint32_t& r3,
                                         uint32_t addr) {
    asm volatile("ldmatrix.sync.aligned.m8n8.x4.trans.shared.b16 {%0,%1,%2,%3}, [%4];"
                 : "=r"(r0), "=r"(r1), "=r"(r2), "=r"(r3) : "r"(addr));
}
__device__ __forceinline__ void cpasync16(uint32_t s, const void* g) {
    asm volatile("cp.async.cg.shared.global [%0], [%1], 16;" :: "r"(s), "l"(g));
}
__device__ __forceinline__ uint32_t smem_u32p(const void* p) {
    uint32_t a;
    asm("{ .reg .u64 t; cvta.to.shared.u64 t, %1; cvt.u32.u64 %0, t; }" : "=r"(a) : "l"(p));
    return a;
}

// Fast exp on the FMA pipe
__device__ __forceinline__ float fexp(float x) {
    x = fmaxf(x, -80.0f);
    float z = fmaf(x, 1.4426950408889634f, 12582912.0f);
    int   ni = __float_as_int(z) - 0x4B400000;
    float fn = z - 12582912.0f;
    float f  = fmaf(x, 1.4426950408889634f, -fn);
    float p = 0.0013333558f;
    p = fmaf(p, f, 0.0096181291f);
    p = fmaf(p, f, 0.0555041087f);
    p = fmaf(p, f, 0.2402265069f);
    p = fmaf(p, f, 0.6931471806f);
    p = fmaf(p, f, 1.0f);
    return __int_as_float(__float_as_int(p) + (ni << 23));
}

// ---------------- denom + lam scalars ----------------
__global__ void k_denom(const float* __restrict__ ts, const float* __restrict__ lam)
{
    float m = 1.0f;
    for (int b = 0; b < Bx; b++) {
        float d = ts[b*Lx + (Lx-1)] - ts[b*Lx + 0];
        m = fmaxf(m, d);
    }
    g_scal[0] = 1.0f / m;
    g_scal[1] = -fabsf(lam[0]);
}

// ---------------- temporal bias precompute ----------------
__global__ __launch_bounds__(256) void k_bias(const float* __restrict__ ts)
{
    long idx = (long)blockIdx.x * 256 + threadIdx.x;
    int  j = (int)(idx & (Lx-1));
    long t = idx >> 11;
    int  i = (int)(t & (Lx-1));
    int  b = (int)(t >> 11);
    float d = fabsf(ts[b*Lx + i] - ts[b*Lx + j]);
    g_bias[idx] = g_scal[1] * log1pf(d * g_scal[0]);
}

// ---------------- tf32 pre-rounding passes ----------------
__global__ __launch_bounds__(256) void k_cvt(const float* __restrict__ s,
                                             float* __restrict__ d)
{
    size_t i = ((size_t)blockIdx.x * 256 + threadIdx.x) * 4;
    float4 v = *(const float4*)(s + i);
    v.x = __uint_as_float(to_tf32(v.x));
    v.y = __uint_as_float(to_tf32(v.y));
    v.z = __uint_as_float(to_tf32(v.z));
    v.w = __uint_as_float(to_tf32(v.w));
    *(float4*)(d + i) = v;
}
__global__ __launch_bounds__(256) void k_cvtw(const float* __restrict__ w0,
                                              const float* __restrict__ w1,
                                              const float* __restrict__ w2,
                                              const float* __restrict__ w3)
{
    const float* s = (blockIdx.z == 0) ? w0 : (blockIdx.z == 1) ? w1 :
                     (blockIdx.z == 2) ? w2 : w3;
    float* d = g_wr + (size_t)blockIdx.z * 1024 * 1024;
    size_t i = ((size_t)blockIdx.x * 256 + threadIdx.x) * 4;
    float4 v = *(const float4*)(s + i);
    v.x = __uint_as_float(to_tf32(v.x));
    v.y = __uint_as_float(to_tf32(v.y));
    v.z = __uint_as_float(to_tf32(v.z));
    v.w = __uint_as_float(to_tf32(v.w));
    *(float4*)(d + i) = v;
}

// ---------------- pack K,V -> bf16 hi/lo in gmem ----------------
__global__ __launch_bounds__(256) void k_packkv()
{
    size_t i = (size_t)blockIdx.x * 256 + threadIdx.x;   // over BHx*Lx*32
    float2 kv = *(const float2*)(g_K + 2 * i);
    split2(kv, g_kh[i], g_kl[i]);
    float2 vv = *(const float2*)(g_V + 2 * i);
    split2(vv, g_vh[i], g_vl[i]);
}

// ---------------- tf32 GEMM: cp.async staging + ldmatrix frags (R10 proven) ----------------
#define BM 128
#define BN 256
#define BK 32
#define LDA 36
#define STG_U32 ((BM + BN) * LDA)
#define GEMM_SMEM (2 * STG_U32 * 4)

template<bool SCATTER>
__global__ __launch_bounds__(256, 1) void k_gemm_tc(
    const float* __restrict__ b0, const float* __restrict__ b1,
    const float* __restrict__ b2, float* __restrict__ outp)
{
    extern __shared__ uint32_t smu[];
    const uint32_t sb = smem_u32p(smu);

    const float* bias;
    float* out;
    int widx;
    if (SCATTER) {
        widx = blockIdx.z;
        if (widx == 0)      { bias = b0; out = g_Q; }
        else if (widx == 1) { bias = b1; out = g_K; }
        else                { bias = b2; out = g_V; }
    } else {
        widx = 3; bias = b0; out = outp;
    }
    const float* A = g_xr;
    const float* W = g_wr + (size_t)widx * 1024 * 1024;

    const int tid = threadIdx.x;
    const int wid = tid >> 5, lane = tid & 31;
    const int wm = wid >> 2, wn = wid & 3;
    const int lr = lane >> 2, lc = lane & 3;
    const int m0 = blockIdx.y * BM;
    const int n0 = blockIdx.x * BN;

    float c[4][8][4];
#pragma unroll
    for (int i = 0; i < 4; i++)
#pragma unroll
        for (int j = 0; j < 8; j++)
#pragma unroll
            for (int q = 0; q < 4; q++) c[i][j][q] = 0.f;

    const int g = lane >> 3, s = lane & 7;
    const uint32_t aoff = ((wm * 64 + ((g & 1) << 3) + s) * LDA + (g >> 1) * 4) * 4;
    const uint32_t boff = (BM * LDA + (wn * 64 + ((g >> 1) << 3) + s) * LDA + (g & 1) * 4) * 4;

    auto load_stage = [&](int st, int k0) {
        const uint32_t base = sb + st * STG_U32 * 4;
#pragma unroll
        for (int t = 0; t < 4; t++) {
            int i = tid + t * 256;
            int r = i >> 3, q = i & 7;
            cpasync16(base + (r * LDA + q * 4) * 4, A + (size_t)(m0 + r) * Dx + k0 + q * 4);
        }
#pragma unroll
        for (int t = 0; t < 8; t++) {
            int i = tid + t * 256;
            int r = i >> 3, q = i & 7;
            cpasync16(base + (BM * LDA + r * LDA + q * 4) * 4,
                      W + (size_t)(n0 + r) * Dx + k0 + q * 4);
        }
        asm volatile("cp.async.commit_group;");
    };

    load_stage(0, 0);

    const int NITER = Dx / BK;
    for (int it = 0; it < NITER; ++it) {
        const int buf = it & 1;
        if (it + 1 < NITER) {
            load_stage((it + 1) & 1, (it + 1) * BK);
            asm volatile("cp.async.wait_group 1;");
        } else {
            asm volatile("cp.async.wait_group 0;");
        }
        __syncthreads();

        const uint32_t base = sb + buf * STG_U32 * 4;
#pragma unroll
        for (int ks = 0; ks < 4; ks++) {
            const uint32_t ko = ks * 32;
            uint32_t af[4][4], bf[8][2];
#pragma unroll
            for (int mt = 0; mt < 4; mt++)
                ldm_x4(af[mt][0], af[mt][1], af[mt][2], af[mt][3],
                       base + aoff + mt * 16 * LDA * 4 + ko);
#pragma unroll
            for (int np = 0; np < 4; np++) {
                uint32_t r0, r1, r2, r3;
                ldm_x4(r0, r1, r2, r3, base + boff + np * 16 * LDA * 4 + ko);
                bf[2*np][0] = r0; bf[2*np][1] = r1;
                bf[2*np+1][0] = r2; bf[2*np+1][1] = r3;
            }
#pragma unroll
            for (int mt = 0; mt < 4; mt++)
#pragma unroll
                for (int nt = 0; nt < 8; nt++)
                    mma16n8k8(c[mt][nt], af[mt], bf[nt]);
        }
        __syncthreads();
    }

#pragma unroll
    for (int mt = 0; mt < 4; mt++) {
        const int mA = m0 + wm * 64 + mt * 16 + lr;
        const int mB = mA + 8;
#pragma unroll
        for (int nt = 0; nt < 8; nt++) {
            const int n = n0 + wn * 64 + nt * 8 + 2 * lc;
            const float bn0 = bias[n], bn1 = bias[n + 1];
            float2 v0 = make_float2(c[mt][nt][0] + bn0, c[mt][nt][1] + bn1);
            float2 v1 = make_float2(c[mt][nt][2] + bn0, c[mt][nt][3] + bn1);
            if (SCATTER) {
                const int h = n >> 6, dk = n & 63;
                const int bA = mA >> 11, lA = mA & (Lx - 1);
                const int bB = mB >> 11, lB = mB & (Lx - 1);
                *(float2*)(out + (((size_t)bA*Hx + h)*Lx + lA)*DKx + dk) = v0;
                *(float2*)(out + (((size_t)bB*Hx + h)*Lx + lB)*DKx + dk) = v1;
            } else {
                *(float2*)(out + (size_t)mA * Dx + n) = v0;
                *(float2*)(out + (size_t)mB * Dx + n) = v1;
            }
        }
    }
}

// ---------------- mma.sync flash attention: pre-packed K/V + cp.async double buffer ----------------
// 128 threads (4 warps), BM=64 queries, key tiles of 64.
// Stage layout per buffer (u32): Kh[64][36] | Kl[64][36] | Vh[64][36] | Vl[64][36]
#define ASTG 9216                      // u32 per stage (4 * 64 * 36)
#define ATTN_SMEM (2 * ASTG * 4)       // 73728 bytes

__global__ __launch_bounds__(128, 3) void k_attn_mma()
{
    extern __shared__ uint32_t smu[];
    const uint32_t sb = smem_u32p(smu);

    const int tid = threadIdx.x;
    const int wid = tid >> 5, lane = tid & 31;
    const int lr = lane >> 2, lc = lane & 3;
    const int qt = gridDim.x - 1 - blockIdx.x;
    const int bh = blockIdx.y;
    const int b = bh >> 4, h = bh & 15;
    const int qi0 = qt * 64;
    const int r0 = wid * 16;
    const int qrA = qi0 + r0 + lr;
    const int qrB = qrA + 8;

    // trans-ldmatrix per-lane offsets into the V region (bytes, rel. to stage base)
    const int vrow = (lane & 7) + (((lane >> 3) & 1) << 3);
    const int vcol = ((lane >> 4) << 3);
    const uint32_t vhrel = 4608 * 4 + vrow * 144 + vcol * 2;
    const uint32_t vlrel = 6912 * 4 + vrow * 144 + vcol * 2;

    const float* Qg = g_Q + (size_t)bh*Lx*DKx;
    const float* biasB = g_bias + (size_t)b*Lx*Lx;
    const uint32_t* gKh = g_kh + (size_t)bh*Lx*32;
    const uint32_t* gKl = g_kl + (size_t)bh*Lx*32;
    const uint32_t* gVh = g_vh + (size_t)bh*Lx*32;
    const uint32_t* gVl = g_vl + (size_t)bh*Lx*32;

    // Q fragments (bf16 hi/lo) in registers for the whole kernel
    uint32_t qH[4][4], qL[4][4];
#pragma unroll
    for (int ks = 0; ks < 4; ks++) {
        const int kb = 16 * ks + 2 * lc;
        float2 v;
        v = *(const float2*)(Qg + (size_t)qrA * DKx + kb);
        split2(v, qH[ks][0], qL[ks][0]);
        v = *(const float2*)(Qg + (size_t)qrB * DKx + kb);
        split2(v, qH[ks][1], qL[ks][1]);
        v = *(const float2*)(Qg + (size_t)qrA * DKx + kb + 8);
        split2(v, qH[ks][2], qL[ks][2]);
        v = *(const float2*)(Qg + (size_t)qrB * DKx + kb + 8);
        split2(v, qH[ks][3], qL[ks][3]);
    }

    // stage loader: 2048 16B-chunks (4 arrays x 64 rows x 8 chunks), 16/thread
    auto load_stage = [&](int st, int kj0) {
        const uint32_t base = sb + st * ASTG * 4;
#pragma unroll
        for (int t = 0; t < 16; t++) {
            int i = tid + t * 128;
            int arr = i >> 9;                 // constant per t (t/4)
            int r = (i >> 3) & 63, cc = i & 7;
            const uint32_t* src = (arr == 0) ? gKh : (arr == 1) ? gKl :
                                  (arr == 2) ? gVh : gVl;
            cpasync16(base + (arr * 2304 + r * 36 + cc * 4) * 4,
                      src + (size_t)(kj0 + r) * 32 + cc * 4);
        }
        asm volatile("cp.async.commit_group;");
    };

    float cO[8][4];
#pragma unroll
    for (int nt = 0; nt < 8; nt++)
#pragma unroll
        for (int q = 0; q < 4; q++) cO[nt][q] = 0.f;
    float mA = -1e30f, mB = -1e30f, lA = 0.f, lB = 0.f;

    const int nkt = qt + 1;
    load_stage(0, 0);

    for (int kt = 0; kt < nkt; kt++) {
        const int buf = kt & 1;
        asm volatile("cp.async.wait_group 0;");
        __syncthreads();      // data ready + all warps done with the other buffer
        if (kt + 1 < nkt) load_stage(1 - buf, (kt + 1) * 64);

        const uint32_t* KhU = smu + buf * ASTG;
        const uint32_t* KlU = KhU + 2304;
        const uint32_t vb = sb + buf * ASTG * 4;
        const int kj0 = kt * 64;

        // ---- S = Q K^T : 3x bf16 ----
        float cS[8][4];
#pragma unroll
        for (int nt = 0; nt < 8; nt++)
#pragma unroll
            for (int q = 0; q < 4; q++) cS[nt][q] = 0.f;

#pragma unroll
        for (int ks = 0; ks < 4; ks++) {
#pragma unroll
            for (int nt = 0; nt < 8; nt++) {
                const uint32_t* ph = KhU + (nt * 8 + lr) * 36 + ks * 8 + lc;
                const uint32_t* pl = KlU + (nt * 8 + lr) * 36 + ks * 8 + lc;
                uint32_t bH0 = ph[0], bH1 = ph[4];
                uint32_t bL0 = pl[0], bL1 = pl[4];
                mma_bf16(cS[nt], qH[ks], bH0, bH1);
                mma_bf16(cS[nt], qH[ks], bL0, bL1);
                mma_bf16(cS[nt], qL[ks], bH0, bH1);
            }
        }

        // ---- bias + causal mask + online softmax ----
        const bool domask = (kt == qt);
        float rmA = -1e30f, rmB = -1e30f;
#pragma unroll
        for (int nt = 0; nt < 8; nt++) {
            const int kc = kj0 + nt * 8 + 2 * lc;
            float2 biA = *(const float2*)(biasB + (size_t)qrA * Lx + kc);
            float2 biB = *(const float2*)(biasB + (size_t)qrB * Lx + kc);
            float v0 = fmaf(cS[nt][0], 0.125f, biA.x);
            float v1 = fmaf(cS[nt][1], 0.125f, biA.y);
            float v2 = fmaf(cS[nt][2], 0.125f, biB.x);
            float v3 = fmaf(cS[nt][3], 0.125f, biB.y);
            if (domask) {
                if (kc     > qrA) v0 = -1e30f;
                if (kc + 1 > qrA) v1 = -1e30f;
                if (kc     > qrB) v2 = -1e30f;
                if (kc + 1 > qrB) v3 = -1e30f;
            }
            cS[nt][0] = v0; cS[nt][1] = v1; cS[nt][2] = v2; cS[nt][3] = v3;
            rmA = fmaxf(rmA, fmaxf(v0, v1));
            rmB = fmaxf(rmB, fmaxf(v2, v3));
        }
        rmA = fmaxf(rmA, __shfl_xor_sync(0xffffffffu, rmA, 1));
        rmA = fmaxf(rmA, __shfl_xor_sync(0xffffffffu, rmA, 2));
        rmB = fmaxf(rmB, __shfl_xor_sync(0xffffffffu, rmB, 1));
        rmB = fmaxf(rmB, __shfl_xor_sync(0xffffffffu, rmB, 2));

        const float mnA = fmaxf(mA, rmA);
        const float mnB = fmaxf(mB, rmB);
        const float scA = fexp(mA - mnA);
        const float scB = fexp(mB - mnB);
        mA = mnA; mB = mnB;

        float rsA = 0.f, rsB = 0.f;
#pragma unroll
        for (int nt = 0; nt < 8; nt++) {
            float p0 = fexp(cS[nt][0] - mnA);
            float p1 = fexp(cS[nt][1] - mnA);
            float p2 = fexp(cS[nt][2] - mnB);
            float p3 = fexp(cS[nt][3] - mnB);
            rsA += p0 + p1;
            rsB += p2 + p3;
            cS[nt][0] = p0; cS[nt][1] = p1; cS[nt][2] = p2; cS[nt][3] = p3;
        }
        rsA += __shfl_xor_sync(0xffffffffu, rsA, 1);
        rsA += __shfl_xor_sync(0xffffffffu, rsA, 2);
        rsB += __shfl_xor_sync(0xffffffffu, rsB, 1);
        rsB += __shfl_xor_sync(0xffffffffu, rsB, 2);
        lA = lA * scA + rsA;
        lB = lB * scB + rsB;
#pragma unroll
        for (int nt = 0; nt < 8; nt++) {
            cO[nt][0] *= scA; cO[nt][1] *= scA;
            cO[nt][2] *= scB; cO[nt][3] *= scB;
        }

        // ---- P -> bf16 hi/lo A-fragments (in registers) ----
        uint32_t aPh[4][4], aPl[4][4];
#pragma unroll
        for (int nt2 = 0; nt2 < 4; nt2++) {
            split2(make_float2(cS[2*nt2][0],   cS[2*nt2][1]),   aPh[nt2][0], aPl[nt2][0]);
            split2(make_float2(cS[2*nt2][2],   cS[2*nt2][3]),   aPh[nt2][1], aPl[nt2][1]);
            split2(make_float2(cS[2*nt2+1][0], cS[2*nt2+1][1]), aPh[nt2][2], aPl[nt2][2]);
            split2(make_float2(cS[2*nt2+1][2], cS[2*nt2+1][3]), aPh[nt2][3], aPl[nt2][3]);
        }

        // ---- O += P @ V : PhVh + PlVh + PhVl, V frags via ldmatrix.trans ----
#pragma unroll
        for (int nt2 = 0; nt2 < 4; nt2++) {
            const uint32_t ko = nt2 * 16 * 144;
#pragma unroll
            for (int dp = 0; dp < 4; dp++) {
                const uint32_t doff = ko + dp * 32;
                uint32_t h0, h1, h2, h3;
                ldm_x4_t(h0, h1, h2, h3, vb + vhrel + doff);
                mma_bf16(cO[2*dp],     aPh[nt2], h0, h1);
                mma_bf16(cO[2*dp + 1], aPh[nt2], h2, h3);
                mma_bf16(cO[2*dp],     aPl[nt2], h0, h1);
                mma_bf16(cO[2*dp + 1], aPl[nt2], h2, h3);
                uint32_t l0, l1, l2, l3;
                ldm_x4_t(l0, l1, l2, l3, vb + vlrel + doff);
                mma_bf16(cO[2*dp],     aPh[nt2], l0, l1);
                mma_bf16(cO[2*dp + 1], aPh[nt2], l2, l3);
            }
        }
    }

    const float invA = 1.0f / lA;
    const float invB = 1.0f / lB;
    float* oA = g_attn + ((size_t)b * Lx + qrA) * Dx + h * DKx;
    float* oB = g_attn + ((size_t)b * Lx + qrB) * Dx + h * DKx;
#pragma unroll
    for (int nt = 0; nt < 8; nt++) {
        const int n = nt * 8 + 2 * lc;
        *(float2*)(oA + n) = make_float2(cO[nt][0] * invA, cO[nt][1] * invA);
        *(float2*)(oB + n) = make_float2(cO[nt][2] * invB, cO[nt][3] * invB);
    }
}

// ---------------- launch ----------------
extern "C" void kernel_launch(void* const* d_in, const int* in_sizes, int n_in,
                              void* d_out, int out_size)
{
    const float* x   = (const float*)d_in[0];
    const float* ts  = (const float*)d_in[1];
    const float* Wq  = (const float*)d_in[4];
    const float* bq  = (const float*)d_in[5];
    const float* Wk  = (const float*)d_in[6];
    const float* bk  = (const float*)d_in[7];
    const float* Wv  = (const float*)d_in[8];
    const float* bv  = (const float*)d_in[9];
    const float* Wo  = (const float*)d_in[10];
    const float* bo  = (const float*)d_in[11];
    const float* lam = (const float*)d_in[12];
    float* out = (float*)d_out;

    float* xr_p; float* attn_p;
    cudaGetSymbolAddress((void**)&xr_p, g_xr);
    cudaGetSymbolAddress((void**)&attn_p, g_attn);

    k_denom<<<1, 1>>>(ts, lam);
    k_bias<<<(Bx*Lx*Lx)/256, 256>>>(ts);

    // tf32 pre-rounding
    k_cvt<<<(4096*1024)/1024, 256>>>(x, xr_p);
    k_cvtw<<<dim3((1024*1024)/1024, 1, 4), 256>>>(Wq, Wk, Wv, Wo);

    cudaFuncSetAttribute(k_gemm_tc<true>,  cudaFuncAttributeMaxDynamicSharedMemorySize, GEMM_SMEM);
    cudaFuncSetAttribute(k_gemm_tc<false>, cudaFuncAttributeMaxDynamicSharedMemorySize, GEMM_SMEM);
    cudaFuncSetAttribute(k_attn_mma, cudaFuncAttributeMaxDynamicSharedMemorySize, ATTN_SMEM);

    // Q/K/V projections
    k_gemm_tc<true><<<dim3(Dx/BN, (Bx*Lx)/BM, 3), 256, GEMM_SMEM>>>(
        bq, bk, bv, nullptr);

    // pack K/V to bf16 hi/lo
    k_packkv<<<(BHx*Lx*32)/256, 256>>>();

    // flash attention
    k_attn_mma<<<dim3(Lx/64, BHx), 128, ATTN_SMEM>>>();

    // round attention output, then output projection
    k_cvt<<<(4096*1024)/1024, 256>>>(attn_p, xr_p);
    k_gemm_tc<false><<<dim3(Dx/BN, (Bx*Lx)/BM, 1), 256, GEMM_SMEM>>>(
        bo, nullptr, nullptr, out);
}